// round 10
// baseline (speedup 1.0000x reference)
#include <cuda_runtime.h>
#include <cuda_bf16.h>
#include <math.h>
#include <stdint.h>

#define NMAX   50000
#define EMAX   1048576
#define EMB    256
#define MID    256
#define OUTD   128
#define SCAN_B 1024
#define NBLK_SCAN ((NMAX + SCAN_B - 1) / SCAN_B)   // 49

// ---- scratch (static device globals; no runtime allocation) ----
__device__ float g_H1[NMAX * MID];     // dis .* (A @ W1)
__device__ float g_H2[NMAX * OUTD];    // dis .* (X1 @ W2)
__device__ float g_dis[NMAX];
__device__ int   g_deg[NMAX];
__device__ int   g_rowptr[NMAX + 1];
__device__ int   g_cur[NMAX];
__device__ int   g_col[EMAX];
__device__ int   g_blocksum[NBLK_SCAN + 1];
// packed bf16 hi/mid planes: uint2 {hi bf16x2, mid bf16x2} per k-pair
__device__ uint2 g_Apk[NMAX * EMB / 2];        // A operand (reused both layers)
__device__ uint2 g_W1pk[(EMB / 2) * MID];      // [kp][n]
__device__ uint2 g_W2pk[(MID / 2) * OUTD];     // [kp][n]

// ----------------------------------------------------------------------------
// degree / normalization
// ----------------------------------------------------------------------------
__global__ void zero_deg_kernel(int n) {
    int i = blockIdx.x * blockDim.x + threadIdx.x;
    if (i < n) g_deg[i] = 0;
}

__global__ void count_deg_kernel(const int* __restrict__ dst, int E) {
    int e = blockIdx.x * blockDim.x + threadIdx.x;
    if (e < E) atomicAdd(&g_deg[dst[e]], 1);
}

__global__ void compute_dis_kernel(int n) {
    int i = blockIdx.x * blockDim.x + threadIdx.x;
    if (i < n) g_dis[i] = rsqrtf((float)(g_deg[i] + 1));
}

// ----------------------------------------------------------------------------
// multi-block exclusive scan of g_deg -> g_rowptr
// ----------------------------------------------------------------------------
__global__ __launch_bounds__(SCAN_B)
void scan_phase1_kernel(int n) {
    __shared__ int s[SCAN_B];
    int i = blockIdx.x * SCAN_B + threadIdx.x;
    int v = (i < n) ? g_deg[i] : 0;
    s[threadIdx.x] = v;
    __syncthreads();
#pragma unroll
    for (int off = 1; off < SCAN_B; off <<= 1) {
        int t = (threadIdx.x >= off) ? s[threadIdx.x - off] : 0;
        __syncthreads();
        s[threadIdx.x] += t;
        __syncthreads();
    }
    if (i < n) g_rowptr[i] = s[threadIdx.x] - v;
    if (threadIdx.x == SCAN_B - 1) g_blocksum[blockIdx.x] = s[SCAN_B - 1];
}

__global__ __launch_bounds__(64)
void scan_phase2_kernel(int nblk) {
    __shared__ int s[64];
    int v = (threadIdx.x < nblk) ? g_blocksum[threadIdx.x] : 0;
    s[threadIdx.x] = v;
    __syncthreads();
#pragma unroll
    for (int off = 1; off < 64; off <<= 1) {
        int t = (threadIdx.x >= off) ? s[threadIdx.x - off] : 0;
        __syncthreads();
        s[threadIdx.x] += t;
        __syncthreads();
    }
    if (threadIdx.x < nblk) g_blocksum[threadIdx.x] = s[threadIdx.x] - v;
    if (threadIdx.x == 63) g_blocksum[nblk] = s[63];
}

__global__ __launch_bounds__(SCAN_B)
void scan_phase3_kernel(int n, int nblk) {
    int i = blockIdx.x * SCAN_B + threadIdx.x;
    if (i < n) {
        int ex = g_rowptr[i] + g_blocksum[blockIdx.x];
        g_rowptr[i] = ex;
        g_cur[i] = ex;
    }
    if (i == 0) g_rowptr[n] = g_blocksum[nblk];
}

// ----------------------------------------------------------------------------
// CSR fill
// ----------------------------------------------------------------------------
__global__ void fill_csr_kernel(const int* __restrict__ src,
                                const int* __restrict__ dst, int E) {
    int e = blockIdx.x * blockDim.x + threadIdx.x;
    if (e < E) {
        int d = dst[e];
        int pos = atomicAdd(&g_cur[d], 1);
        g_col[pos] = src[e];
    }
}

// ----------------------------------------------------------------------------
// bf16 hi/mid split helpers
// ----------------------------------------------------------------------------
__device__ __forceinline__ void split2(float f0, float f1, uint32_t& hi, uint32_t& mid) {
    __nv_bfloat16 h0 = __float2bfloat16(f0);
    __nv_bfloat16 h1 = __float2bfloat16(f1);
    float r0 = f0 - __bfloat162float(h0);
    float r1 = f1 - __bfloat162float(h1);
    __nv_bfloat162 hp = __nv_bfloat162(h0, h1);
    __nv_bfloat162 mp = __nv_bfloat162(__float2bfloat16(r0), __float2bfloat16(r1));
    hi  = *(uint32_t*)&hp;
    mid = *(uint32_t*)&mp;
}

// A [M][K] fp32 -> Apk [M][K/2] uint2 (one uint4 per float4)
__global__ void conv_a_kernel(const float* __restrict__ X, uint2* __restrict__ Apk,
                              int total4) {
    int i = blockIdx.x * blockDim.x + threadIdx.x;
    if (i >= total4) return;
    float4 v = ((const float4*)X)[i];
    uint32_t h01, m01, h23, m23;
    split2(v.x, v.y, h01, m01);
    split2(v.z, v.w, h23, m23);
    ((uint4*)Apk)[i] = make_uint4(h01, m01, h23, m23);
}

// W [K][N] fp32 -> Wpk [K/2][N] uint2
__global__ void conv_w_kernel(const float* __restrict__ W, uint2* __restrict__ Wpk,
                              int K, int N) {
    int idx = blockIdx.x * blockDim.x + threadIdx.x;
    if (idx >= (K / 2) * N) return;
    int kp = idx / N;
    int n  = idx % N;
    float x0 = W[(size_t)(2 * kp) * N + n];
    float x1 = W[(size_t)(2 * kp + 1) * N + n];
    uint32_t hi, mid;
    split2(x0, x1, hi, mid);
    Wpk[idx] = make_uint2(hi, mid);
}

// ----------------------------------------------------------------------------
// 3x-bf16 mma.sync GEMM (m16n8k16) on pre-packed operands:
//   C[m,:] = dis[m] * (A @ B)[m,:]
// BM=128, BN=128, BK=32 (16 kpairs/chunk); 256 threads, 8 warps (4x2),
// warp tile 32x64. C = Ah*Bh + Ah*Bm + Am*Bh, fp32 accum.
// ----------------------------------------------------------------------------
#define BM 128
#define BN 128
#define KPC 16    // kpairs per chunk (BK=32)
#define ASTR 20   // uint2 stride: 20 mod 16 = 4 -> conflict-free frag LDS.64
#define BSTR 132  // uint2 stride: 132 mod 16 = 4 -> conflict-free frag LDS.64

__device__ __forceinline__ void mma_bf16(float* d, const uint32_t* a, const uint32_t* b) {
    asm volatile(
        "mma.sync.aligned.m16n8k16.row.col.f32.bf16.bf16.f32 "
        "{%0,%1,%2,%3}, {%4,%5,%6,%7}, {%8,%9}, {%0,%1,%2,%3};\n"
        : "+f"(d[0]), "+f"(d[1]), "+f"(d[2]), "+f"(d[3])
        : "r"(a[0]), "r"(a[1]), "r"(a[2]), "r"(a[3]),
          "r"(b[0]), "r"(b[1]));
}

__global__ __launch_bounds__(256)
void gemm_pk_kernel(const uint2* __restrict__ Apk, const uint2* __restrict__ Bpk,
                    float* __restrict__ C, int M, int N, int K) {
    __shared__ __align__(16) uint2 As[BM][ASTR];    // 20 KB
    __shared__ __align__(16) uint2 Bs[KPC][BSTR];   // 16.5 KB

    int tid  = threadIdx.x;
    int lane = tid & 31;
    int wid  = tid >> 5;
    int gID  = lane >> 2;         // 0..7
    int tig  = lane & 3;          // 0..3
    int warpM = wid >> 1;         // 0..3 -> 32-row slab
    int warpN = wid & 1;          // 0..1 -> 64-col slab

    int m0 = blockIdx.y * BM;
    int n0 = blockIdx.x * BN;

    int nKP = K / 2;              // kpairs per row

    // A loader: row = tid>>1, 8 kpairs (half = tid&1)
    int aRow = tid >> 1;
    int akp  = (tid & 1) * 8;
    // B loader: kprow = tid>>4 (0..15), 8 n columns
    int bkp  = tid >> 4;
    int bn   = (tid & 15) * 8;

    float acc[2][8][4];
#pragma unroll
    for (int mt = 0; mt < 2; mt++)
#pragma unroll
        for (int nt = 0; nt < 8; nt++)
#pragma unroll
            for (int r = 0; r < 4; r++) acc[mt][nt][r] = 0.0f;

    int nC = K / (2 * KPC);       // chunks of 16 kpairs

    for (int c = 0; c < nC; c++) {
        if (c) __syncthreads();
        // ---- load chunk ----
        {
            int gm = m0 + aRow;
            const uint4* ap = (const uint4*)(Apk + (size_t)gm * nKP + c * KPC + akp);
            uint4 z = make_uint4(0, 0, 0, 0);
#pragma unroll
            for (int i = 0; i < 4; i++) {
                uint4 v = (gm < M) ? ap[i] : z;
                *(uint4*)&As[aRow][akp + 2 * i] = v;
            }
            const uint4* bp = (const uint4*)(Bpk + (size_t)(c * KPC + bkp) * N + n0 + bn);
#pragma unroll
            for (int i = 0; i < 4; i++) {
                *(uint4*)&Bs[bkp][bn + 2 * i] = bp[i];
            }
        }
        __syncthreads();

        // ---- compute: 2 k16-steps per chunk ----
#pragma unroll
        for (int ks = 0; ks < 2; ks++) {
            int kpb = ks * 8;
            uint32_t ah[2][4], am[2][4];
#pragma unroll
            for (int mt = 0; mt < 2; mt++) {
                int r = warpM * 32 + mt * 16 + gID;
                uint2 q0 = As[r][kpb + tig];
                uint2 q1 = As[r + 8][kpb + tig];
                uint2 q2 = As[r][kpb + tig + 4];
                uint2 q3 = As[r + 8][kpb + tig + 4];
                ah[mt][0] = q0.x; am[mt][0] = q0.y;
                ah[mt][1] = q1.x; am[mt][1] = q1.y;
                ah[mt][2] = q2.x; am[mt][2] = q2.y;
                ah[mt][3] = q3.x; am[mt][3] = q3.y;
            }
#pragma unroll
            for (int nt = 0; nt < 8; nt++) {
                int n = warpN * 64 + nt * 8 + gID;
                uint2 p0 = Bs[kpb + tig][n];
                uint2 p1 = Bs[kpb + tig + 4][n];
                uint32_t bh[2] = {p0.x, p1.x};
                uint32_t bm[2] = {p0.y, p1.y};
#pragma unroll
                for (int mt = 0; mt < 2; mt++) {
                    mma_bf16(acc[mt][nt], ah[mt], bh);
                    mma_bf16(acc[mt][nt], ah[mt], bm);
                    mma_bf16(acc[mt][nt], am[mt], bh);
                }
            }
        }
    }

    // ---- epilogue: scale by dis[row], store ----
#pragma unroll
    for (int mt = 0; mt < 2; mt++) {
        int row0 = m0 + warpM * 32 + mt * 16 + gID;
        int row1 = row0 + 8;
        float s0 = (row0 < M) ? g_dis[row0] : 0.0f;
        float s1 = (row1 < M) ? g_dis[row1] : 0.0f;
#pragma unroll
        for (int nt = 0; nt < 8; nt++) {
            int col = n0 + warpN * 64 + nt * 8 + tig * 2;
            if (row0 < M) {
                float2 v = {acc[mt][nt][0] * s0, acc[mt][nt][1] * s0};
                *(float2*)(C + (size_t)row0 * N + col) = v;
            }
            if (row1 < M) {
                float2 v = {acc[mt][nt][2] * s1, acc[mt][nt][3] * s1};
                *(float2*)(C + (size_t)row1 * N + col) = v;
            }
        }
    }
}

// ----------------------------------------------------------------------------
// pull aggregation + bias + exact GELU.
// PACK=true: write packed bf16 hi/mid uint4 (GEMM A-operand format).
// PACK=false: write fp32.
// ----------------------------------------------------------------------------
__device__ __forceinline__ float4 f4add(float4 a, float4 b) {
    return make_float4(a.x + b.x, a.y + b.y, a.z + b.z, a.w + b.w);
}

template <int TPG, bool PACK>
__global__ __launch_bounds__(256)
void agg_gelu_kernel(const float* __restrict__ Hs, const float* __restrict__ bias,
                     void* __restrict__ Out, int n) {
    int gid = (int)(blockIdx.x * blockDim.x + threadIdx.x) / TPG;
    int t   = threadIdx.x & (TPG - 1);
    if (gid >= n) return;

    const float4* H4 = (const float4*)Hs;
    int beg = g_rowptr[gid];
    int end = g_rowptr[gid + 1];

    float4 a0 = H4[(size_t)gid * TPG + t];
    float4 a1 = make_float4(0.f, 0.f, 0.f, 0.f);
    float4 a2 = a1, a3 = a1;

    int p = beg;
    for (; p + 3 < end; p += 4) {
        int s0 = g_col[p];
        int s1 = g_col[p + 1];
        int s2 = g_col[p + 2];
        int s3 = g_col[p + 3];
        a0 = f4add(a0, H4[(size_t)s0 * TPG + t]);
        a1 = f4add(a1, H4[(size_t)s1 * TPG + t]);
        a2 = f4add(a2, H4[(size_t)s2 * TPG + t]);
        a3 = f4add(a3, H4[(size_t)s3 * TPG + t]);
    }
    for (; p < end; p++)
        a0 = f4add(a0, H4[(size_t)g_col[p] * TPG + t]);

    float4 acc = f4add(f4add(a0, a1), f4add(a2, a3));
    float dd = g_dis[gid];
    float4 bb = ((const float4*)bias)[t];

    float x0 = acc.x * dd + bb.x;
    float x1 = acc.y * dd + bb.y;
    float x2 = acc.z * dd + bb.z;
    float x3 = acc.w * dd + bb.w;
    const float inv_sqrt2 = 0.70710678118654752f;
    float o0 = 0.5f * x0 * (1.0f + erff(x0 * inv_sqrt2));
    float o1 = 0.5f * x1 * (1.0f + erff(x1 * inv_sqrt2));
    float o2 = 0.5f * x2 * (1.0f + erff(x2 * inv_sqrt2));
    float o3 = 0.5f * x3 * (1.0f + erff(x3 * inv_sqrt2));

    if (PACK) {
        uint32_t h01, m01, h23, m23;
        split2(o0, o1, h01, m01);
        split2(o2, o3, h23, m23);
        ((uint4*)Out)[(size_t)gid * TPG + t] = make_uint4(h01, m01, h23, m23);
    } else {
        ((float4*)Out)[(size_t)gid * TPG + t] = make_float4(o0, o1, o2, o3);
    }
}

// ----------------------------------------------------------------------------
extern "C" void kernel_launch(void* const* d_in, const int* in_sizes, int n_in,
                              void* d_out, int out_size) {
    const float* node_emb = (const float*)d_in[0];   // [N, 256]
    const float* W1       = (const float*)d_in[1];   // [256, 256]
    const float* b1       = (const float*)d_in[2];   // [256]
    const float* W2       = (const float*)d_in[3];   // [256, 128]
    const float* b2       = (const float*)d_in[4];   // [128]
    const int*   eidx     = (const int*)d_in[5];     // [2, E]

    int N = in_sizes[0] / EMB;
    int E = in_sizes[5] / 2;
    const int* src = eidx;
    const int* dst = eidx + E;

    float* H1 = nullptr; float* H2 = nullptr;
    uint2 *Apk = nullptr, *W1pk = nullptr, *W2pk = nullptr;
    cudaGetSymbolAddress((void**)&H1, g_H1);
    cudaGetSymbolAddress((void**)&H2, g_H2);
    cudaGetSymbolAddress((void**)&Apk, g_Apk);
    cudaGetSymbolAddress((void**)&W1pk, g_W1pk);
    cudaGetSymbolAddress((void**)&W2pk, g_W2pk);
    float* outp = (float*)d_out;

    int nblk_scan = (N + SCAN_B - 1) / SCAN_B;

    // ---- degrees, normalization, CSR ----
    zero_deg_kernel<<<(N + 255) / 256, 256>>>(N);
    count_deg_kernel<<<(E + 255) / 256, 256>>>(dst, E);
    compute_dis_kernel<<<(N + 255) / 256, 256>>>(N);
    scan_phase1_kernel<<<nblk_scan, SCAN_B>>>(N);
    scan_phase2_kernel<<<1, 64>>>(nblk_scan);
    scan_phase3_kernel<<<nblk_scan, SCAN_B>>>(N, nblk_scan);
    fill_csr_kernel<<<(E + 255) / 256, 256>>>(src, dst, E);

    // ---- pack operands ----
    conv_w_kernel<<<((EMB / 2) * MID + 255) / 256, 256>>>(W1, W1pk, EMB, MID);
    conv_w_kernel<<<((MID / 2) * OUTD + 255) / 256, 256>>>(W2, W2pk, MID, OUTD);
    conv_a_kernel<<<(N * EMB / 4 + 255) / 256, 256>>>(node_emb, Apk, N * EMB / 4);

    // ---- layer 1: H1 = dis .* (A @ W1); X1pk = pack(gelu(agg + b1)) ----
    {
        dim3 grid(MID / BN, (N + BM - 1) / BM);
        gemm_pk_kernel<<<grid, 256>>>(Apk, W1pk, H1, N, MID, EMB);
    }
    {
        const int TPG = MID / 4;   // 64
        int groups_per_blk = 256 / TPG;
        int nblk = (N + groups_per_blk - 1) / groups_per_blk;
        agg_gelu_kernel<TPG, true><<<nblk, 256>>>(H1, b1, Apk, N);
    }

    // ---- layer 2: H2 = dis .* (X1 @ W2); out = gelu(agg + b2) ----
    {
        dim3 grid(OUTD / BN, (N + BM - 1) / BM);
        gemm_pk_kernel<<<grid, 256>>>(Apk, W2pk, H2, N, OUTD, MID);
    }
    {
        const int TPG = OUTD / 4;  // 32
        int groups_per_blk = 256 / TPG;
        int nblk = (N + groups_per_blk - 1) / groups_per_blk;
        agg_gelu_kernel<TPG, false><<<nblk, 256>>>(H2, b2, outp, N);
    }
}

// round 11
// speedup vs baseline: 1.0186x; 1.0186x over previous
#include <cuda_runtime.h>
#include <cuda_bf16.h>
#include <math.h>
#include <stdint.h>

#define NMAX   50000
#define EMAX   1048576
#define EMB    256
#define MID    256
#define OUTD   128
#define SCAN_B 1024
#define NBLK_SCAN ((NMAX + SCAN_B - 1) / SCAN_B)   // 49

// ---- scratch (static device globals; no runtime allocation) ----
__device__ float g_H1[NMAX * MID];     // dis .* (A @ W1)
__device__ float g_H2[NMAX * OUTD];    // dis .* (X1 @ W2)
__device__ float g_dis[NMAX];
__device__ int   g_deg[NMAX];
__device__ int   g_rowptr[NMAX + 1];
__device__ int   g_cur[NMAX];
__device__ int   g_col[EMAX];
__device__ int   g_blocksum[NBLK_SCAN + 1];
// packed bf16 hi/mid planes: uint2 {hi bf16x2, mid bf16x2} per k-pair
__device__ uint2 g_Apk[NMAX * EMB / 2];        // A operand (reused both layers)
__device__ uint2 g_W1pk[(EMB / 2) * MID];      // [kp][n]
__device__ uint2 g_W2pk[(MID / 2) * OUTD];     // [kp][n]

// ----------------------------------------------------------------------------
// degree / normalization
// ----------------------------------------------------------------------------
__global__ void zero_deg_kernel(int n) {
    int i = blockIdx.x * blockDim.x + threadIdx.x;
    if (i < n) g_deg[i] = 0;
}

__global__ void count_deg_kernel(const int* __restrict__ dst, int E) {
    int e = blockIdx.x * blockDim.x + threadIdx.x;
    if (e < E) atomicAdd(&g_deg[dst[e]], 1);
}

__global__ void compute_dis_kernel(int n) {
    int i = blockIdx.x * blockDim.x + threadIdx.x;
    if (i < n) g_dis[i] = rsqrtf((float)(g_deg[i] + 1));
}

// ----------------------------------------------------------------------------
// multi-block exclusive scan of g_deg -> g_rowptr
// ----------------------------------------------------------------------------
__global__ __launch_bounds__(SCAN_B)
void scan_phase1_kernel(int n) {
    __shared__ int s[SCAN_B];
    int i = blockIdx.x * SCAN_B + threadIdx.x;
    int v = (i < n) ? g_deg[i] : 0;
    s[threadIdx.x] = v;
    __syncthreads();
#pragma unroll
    for (int off = 1; off < SCAN_B; off <<= 1) {
        int t = (threadIdx.x >= off) ? s[threadIdx.x - off] : 0;
        __syncthreads();
        s[threadIdx.x] += t;
        __syncthreads();
    }
    if (i < n) g_rowptr[i] = s[threadIdx.x] - v;
    if (threadIdx.x == SCAN_B - 1) g_blocksum[blockIdx.x] = s[SCAN_B - 1];
}

__global__ __launch_bounds__(64)
void scan_phase2_kernel(int nblk) {
    __shared__ int s[64];
    int v = (threadIdx.x < nblk) ? g_blocksum[threadIdx.x] : 0;
    s[threadIdx.x] = v;
    __syncthreads();
#pragma unroll
    for (int off = 1; off < 64; off <<= 1) {
        int t = (threadIdx.x >= off) ? s[threadIdx.x - off] : 0;
        __syncthreads();
        s[threadIdx.x] += t;
        __syncthreads();
    }
    if (threadIdx.x < nblk) g_blocksum[threadIdx.x] = s[threadIdx.x] - v;
    if (threadIdx.x == 63) g_blocksum[nblk] = s[63];
}

__global__ __launch_bounds__(SCAN_B)
void scan_phase3_kernel(int n, int nblk) {
    int i = blockIdx.x * SCAN_B + threadIdx.x;
    if (i < n) {
        int ex = g_rowptr[i] + g_blocksum[blockIdx.x];
        g_rowptr[i] = ex;
        g_cur[i] = ex;
    }
    if (i == 0) g_rowptr[n] = g_blocksum[nblk];
}

// ----------------------------------------------------------------------------
// CSR fill
// ----------------------------------------------------------------------------
__global__ void fill_csr_kernel(const int* __restrict__ src,
                                const int* __restrict__ dst, int E) {
    int e = blockIdx.x * blockDim.x + threadIdx.x;
    if (e < E) {
        int d = dst[e];
        int pos = atomicAdd(&g_cur[d], 1);
        g_col[pos] = src[e];
    }
}

// ----------------------------------------------------------------------------
// bf16 hi/mid split helpers
// ----------------------------------------------------------------------------
__device__ __forceinline__ void split2(float f0, float f1, uint32_t& hi, uint32_t& mid) {
    __nv_bfloat16 h0 = __float2bfloat16(f0);
    __nv_bfloat16 h1 = __float2bfloat16(f1);
    float r0 = f0 - __bfloat162float(h0);
    float r1 = f1 - __bfloat162float(h1);
    __nv_bfloat162 hp = __nv_bfloat162(h0, h1);
    __nv_bfloat162 mp = __nv_bfloat162(__float2bfloat16(r0), __float2bfloat16(r1));
    hi  = *(uint32_t*)&hp;
    mid = *(uint32_t*)&mp;
}

// A [M][K] fp32 -> Apk [M][K/2] uint2 (one uint4 per float4)
__global__ void conv_a_kernel(const float* __restrict__ X, uint2* __restrict__ Apk,
                              int total4) {
    int i = blockIdx.x * blockDim.x + threadIdx.x;
    if (i >= total4) return;
    float4 v = ((const float4*)X)[i];
    uint32_t h01, m01, h23, m23;
    split2(v.x, v.y, h01, m01);
    split2(v.z, v.w, h23, m23);
    ((uint4*)Apk)[i] = make_uint4(h01, m01, h23, m23);
}

// W [K][N] fp32 -> Wpk [K/2][N] uint2
__global__ void conv_w_kernel(const float* __restrict__ W, uint2* __restrict__ Wpk,
                              int K, int N) {
    int idx = blockIdx.x * blockDim.x + threadIdx.x;
    if (idx >= (K / 2) * N) return;
    int kp = idx / N;
    int n  = idx % N;
    float x0 = W[(size_t)(2 * kp) * N + n];
    float x1 = W[(size_t)(2 * kp + 1) * N + n];
    uint32_t hi, mid;
    split2(x0, x1, hi, mid);
    Wpk[idx] = make_uint2(hi, mid);
}

// ----------------------------------------------------------------------------
// 3x-bf16 mma.sync GEMM (m16n8k16) on pre-packed operands, R9 geometry:
//   C[m,:] = dis[m] * (A @ B)[m,:]
// BM=128, BN=64, BK=16 (8 kpairs/chunk); 256 threads, 8 warps (4x2),
// warp tile 32x32, register prefetch. C = Ah*Bh + Ah*Bm + Am*Bh, fp32 accum.
// ----------------------------------------------------------------------------
#define BM 128
#define BN 64
#define KPC 8     // kpairs per chunk (BK=16)
#define ASTR 12   // uint2 per A row: (12g+t) mod 16 distinct per half-warp
#define BSTR 68   // uint2 per B kpair row: (68t+n) mod 16 distinct per half-warp

__device__ __forceinline__ void mma_bf16(float* d, const uint32_t* a, const uint32_t* b) {
    asm volatile(
        "mma.sync.aligned.m16n8k16.row.col.f32.bf16.bf16.f32 "
        "{%0,%1,%2,%3}, {%4,%5,%6,%7}, {%8,%9}, {%0,%1,%2,%3};\n"
        : "+f"(d[0]), "+f"(d[1]), "+f"(d[2]), "+f"(d[3])
        : "r"(a[0]), "r"(a[1]), "r"(a[2]), "r"(a[3]),
          "r"(b[0]), "r"(b[1]));
}

__global__ __launch_bounds__(256)
void gemm_pk_kernel(const uint2* __restrict__ Apk, const uint2* __restrict__ Bpk,
                    float* __restrict__ C, int M, int N, int K) {
    __shared__ __align__(16) uint2 As[BM][ASTR];    // 12 KB
    __shared__ __align__(16) uint2 Bs[KPC][BSTR];   // 4.25 KB

    int tid  = threadIdx.x;
    int lane = tid & 31;
    int wid  = tid >> 5;
    int gID  = lane >> 2;         // 0..7
    int tig  = lane & 3;          // 0..3
    int warpM = wid >> 1;         // 0..3 -> 32-row slab
    int warpN = wid & 1;          // 0..1 -> 32-col slab

    int m0 = blockIdx.y * BM;
    int n0 = blockIdx.x * BN;

    int nKP = K / 2;              // kpairs per A row

    // A loader: row = tid>>1, 4 kpairs (half = tid&1)  -> 2 uint4
    int aRow = tid >> 1;
    int akp  = (tid & 1) * 4;
    // B loader: kprow = tid>>5 (0..7), 2 n columns -> 1 uint4
    int bkp  = tid >> 5;
    int bn   = (tid & 31) * 2;

    float acc[2][4][4];
#pragma unroll
    for (int mt = 0; mt < 2; mt++)
#pragma unroll
        for (int nt = 0; nt < 4; nt++)
#pragma unroll
            for (int r = 0; r < 4; r++) acc[mt][nt][r] = 0.0f;

    int nC = K / 16;              // chunks of 8 kpairs

    uint4 pa0, pa1, pb;
    // prefetch chunk 0
    {
        int gm = m0 + aRow;
        if (gm < M) {
            const uint4* ap = (const uint4*)(Apk + (size_t)gm * nKP + akp);
            pa0 = ap[0];
            pa1 = ap[1];
        } else {
            pa0 = pa1 = make_uint4(0, 0, 0, 0);
        }
        pb = *(const uint4*)(Bpk + (size_t)bkp * N + n0 + bn);
    }

    for (int c = 0; c < nC; c++) {
        // ---- store prefetched chunk to smem ----
        *(uint4*)&As[aRow][akp]     = pa0;
        *(uint4*)&As[aRow][akp + 2] = pa1;
        *(uint4*)&Bs[bkp][bn]       = pb;
        __syncthreads();

        // ---- prefetch next chunk ----
        if (c + 1 < nC) {
            int kp0 = (c + 1) * KPC;
            int gm = m0 + aRow;
            if (gm < M) {
                const uint4* ap = (const uint4*)(Apk + (size_t)gm * nKP + kp0 + akp);
                pa0 = ap[0];
                pa1 = ap[1];
            } else {
                pa0 = pa1 = make_uint4(0, 0, 0, 0);
            }
            pb = *(const uint4*)(Bpk + (size_t)(kp0 + bkp) * N + n0 + bn);
        }

        // ---- compute: one m16n8k16 k-step covers the whole chunk ----
        {
            uint32_t ah[2][4], am[2][4];
#pragma unroll
            for (int mt = 0; mt < 2; mt++) {
                int r = warpM * 32 + mt * 16 + gID;
                uint2 q0 = As[r][tig];
                uint2 q1 = As[r + 8][tig];
                uint2 q2 = As[r][tig + 4];
                uint2 q3 = As[r + 8][tig + 4];
                ah[mt][0] = q0.x; am[mt][0] = q0.y;
                ah[mt][1] = q1.x; am[mt][1] = q1.y;
                ah[mt][2] = q2.x; am[mt][2] = q2.y;
                ah[mt][3] = q3.x; am[mt][3] = q3.y;
            }
            uint32_t bh[4][2], bm[4][2];
#pragma unroll
            for (int nt = 0; nt < 4; nt++) {
                int n = warpN * 32 + nt * 8 + gID;
                uint2 p0 = Bs[tig][n];
                uint2 p1 = Bs[tig + 4][n];
                bh[nt][0] = p0.x; bm[nt][0] = p0.y;
                bh[nt][1] = p1.x; bm[nt][1] = p1.y;
            }
#pragma unroll
            for (int mt = 0; mt < 2; mt++)
#pragma unroll
                for (int nt = 0; nt < 4; nt++) {
                    mma_bf16(acc[mt][nt], ah[mt], bh[nt]);
                    mma_bf16(acc[mt][nt], ah[mt], bm[nt]);
                    mma_bf16(acc[mt][nt], am[mt], bh[nt]);
                }
        }
        __syncthreads();
    }

    // ---- epilogue: scale by dis[row], store ----
#pragma unroll
    for (int mt = 0; mt < 2; mt++) {
        int row0 = m0 + warpM * 32 + mt * 16 + gID;
        int row1 = row0 + 8;
        float s0 = (row0 < M) ? g_dis[row0] : 0.0f;
        float s1 = (row1 < M) ? g_dis[row1] : 0.0f;
#pragma unroll
        for (int nt = 0; nt < 4; nt++) {
            int col = n0 + warpN * 32 + nt * 8 + tig * 2;
            if (row0 < M) {
                float2 v = {acc[mt][nt][0] * s0, acc[mt][nt][1] * s0};
                *(float2*)(C + (size_t)row0 * N + col) = v;
            }
            if (row1 < M) {
                float2 v = {acc[mt][nt][2] * s1, acc[mt][nt][3] * s1};
                *(float2*)(C + (size_t)row1 * N + col) = v;
            }
        }
    }
}

// ----------------------------------------------------------------------------
// pull aggregation + bias + exact GELU.
// PACK=true: write packed bf16 hi/mid uint4 (GEMM A-operand format).
// ----------------------------------------------------------------------------
__device__ __forceinline__ float4 f4add(float4 a, float4 b) {
    return make_float4(a.x + b.x, a.y + b.y, a.z + b.z, a.w + b.w);
}

template <int TPG, bool PACK>
__global__ __launch_bounds__(256)
void agg_gelu_kernel(const float* __restrict__ Hs, const float* __restrict__ bias,
                     void* __restrict__ Out, int n) {
    int gid = (int)(blockIdx.x * blockDim.x + threadIdx.x) / TPG;
    int t   = threadIdx.x & (TPG - 1);
    if (gid >= n) return;

    const float4* H4 = (const float4*)Hs;
    int beg = g_rowptr[gid];
    int end = g_rowptr[gid + 1];

    float4 a0 = H4[(size_t)gid * TPG + t];
    float4 a1 = make_float4(0.f, 0.f, 0.f, 0.f);
    float4 a2 = a1, a3 = a1;

    int p = beg;
    for (; p + 3 < end; p += 4) {
        int s0 = g_col[p];
        int s1 = g_col[p + 1];
        int s2 = g_col[p + 2];
        int s3 = g_col[p + 3];
        a0 = f4add(a0, H4[(size_t)s0 * TPG + t]);
        a1 = f4add(a1, H4[(size_t)s1 * TPG + t]);
        a2 = f4add(a2, H4[(size_t)s2 * TPG + t]);
        a3 = f4add(a3, H4[(size_t)s3 * TPG + t]);
    }
    for (; p < end; p++)
        a0 = f4add(a0, H4[(size_t)g_col[p] * TPG + t]);

    float4 acc = f4add(f4add(a0, a1), f4add(a2, a3));
    float dd = g_dis[gid];
    float4 bb = ((const float4*)bias)[t];

    float x0 = acc.x * dd + bb.x;
    float x1 = acc.y * dd + bb.y;
    float x2 = acc.z * dd + bb.z;
    float x3 = acc.w * dd + bb.w;
    const float inv_sqrt2 = 0.70710678118654752f;
    float o0 = 0.5f * x0 * (1.0f + erff(x0 * inv_sqrt2));
    float o1 = 0.5f * x1 * (1.0f + erff(x1 * inv_sqrt2));
    float o2 = 0.5f * x2 * (1.0f + erff(x2 * inv_sqrt2));
    float o3 = 0.5f * x3 * (1.0f + erff(x3 * inv_sqrt2));

    if (PACK) {
        uint32_t h01, m01, h23, m23;
        split2(o0, o1, h01, m01);
        split2(o2, o3, h23, m23);
        ((uint4*)Out)[(size_t)gid * TPG + t] = make_uint4(h01, m01, h23, m23);
    } else {
        ((float4*)Out)[(size_t)gid * TPG + t] = make_float4(o0, o1, o2, o3);
    }
}

// ----------------------------------------------------------------------------
extern "C" void kernel_launch(void* const* d_in, const int* in_sizes, int n_in,
                              void* d_out, int out_size) {
    const float* node_emb = (const float*)d_in[0];   // [N, 256]
    const float* W1       = (const float*)d_in[1];   // [256, 256]
    const float* b1       = (const float*)d_in[2];   // [256]
    const float* W2       = (const float*)d_in[3];   // [256, 128]
    const float* b2       = (const float*)d_in[4];   // [128]
    const int*   eidx     = (const int*)d_in[5];     // [2, E]

    int N = in_sizes[0] / EMB;
    int E = in_sizes[5] / 2;
    const int* src = eidx;
    const int* dst = eidx + E;

    float* H1 = nullptr; float* H2 = nullptr;
    uint2 *Apk = nullptr, *W1pk = nullptr, *W2pk = nullptr;
    cudaGetSymbolAddress((void**)&H1, g_H1);
    cudaGetSymbolAddress((void**)&H2, g_H2);
    cudaGetSymbolAddress((void**)&Apk, g_Apk);
    cudaGetSymbolAddress((void**)&W1pk, g_W1pk);
    cudaGetSymbolAddress((void**)&W2pk, g_W2pk);
    float* outp = (float*)d_out;

    int nblk_scan = (N + SCAN_B - 1) / SCAN_B;

    // ---- degrees, normalization, CSR ----
    zero_deg_kernel<<<(N + 255) / 256, 256>>>(N);
    count_deg_kernel<<<(E + 255) / 256, 256>>>(dst, E);
    compute_dis_kernel<<<(N + 255) / 256, 256>>>(N);
    scan_phase1_kernel<<<nblk_scan, SCAN_B>>>(N);
    scan_phase2_kernel<<<1, 64>>>(nblk_scan);
    scan_phase3_kernel<<<nblk_scan, SCAN_B>>>(N, nblk_scan);
    fill_csr_kernel<<<(E + 255) / 256, 256>>>(src, dst, E);

    // ---- pack operands ----
    conv_w_kernel<<<((EMB / 2) * MID + 255) / 256, 256>>>(W1, W1pk, EMB, MID);
    conv_w_kernel<<<((MID / 2) * OUTD + 255) / 256, 256>>>(W2, W2pk, MID, OUTD);
    conv_a_kernel<<<(N * EMB / 4 + 255) / 256, 256>>>(node_emb, Apk, N * EMB / 4);

    // ---- layer 1: H1 = dis .* (A @ W1); X1pk = pack(gelu(agg + b1)) ----
    {
        dim3 grid(MID / BN, (N + BM - 1) / BM);
        gemm_pk_kernel<<<grid, 256>>>(Apk, W1pk, H1, N, MID, EMB);
    }
    {
        const int TPG = MID / 4;   // 64
        int groups_per_blk = 256 / TPG;
        int nblk = (N + groups_per_blk - 1) / groups_per_blk;
        agg_gelu_kernel<TPG, true><<<nblk, 256>>>(H1, b1, Apk, N);
    }

    // ---- layer 2: H2 = dis .* (X1 @ W2); out = gelu(agg + b2) ----
    {
        dim3 grid(OUTD / BN, (N + BM - 1) / BM);
        gemm_pk_kernel<<<grid, 256>>>(Apk, W2pk, H2, N, OUTD, MID);
    }
    {
        const int TPG = OUTD / 4;  // 32
        int groups_per_blk = 256 / TPG;
        int nblk = (N + groups_per_blk - 1) / groups_per_blk;
        agg_gelu_kernel<TPG, false><<<nblk, 256>>>(H2, b2, outp, N);
    }
}

// round 12
// speedup vs baseline: 1.0346x; 1.0157x over previous
#include <cuda_runtime.h>
#include <cuda_bf16.h>
#include <math.h>
#include <stdint.h>

#define NMAX   50000
#define EMAX   1048576
#define EMB    256
#define MID    256
#define OUTD   128
#define SCAN_B 1024
#define NBLK_SCAN ((NMAX + SCAN_B - 1) / SCAN_B)   // 49

// ---- scratch (static device globals; no runtime allocation) ----
__device__ float g_H1[NMAX * MID];     // node_emb @ W1 (unscaled)
__device__ float g_A1[NMAX * MID];     // gelu(agg) -> layer-2 input
__device__ float g_H2[NMAX * OUTD];    // X1 @ W2 (unscaled)
__device__ float g_dis[NMAX];          // D^-1/2 (in-degree + self loop)
__device__ int   g_deg[NMAX];
__device__ int   g_rowptr[NMAX + 1];
__device__ int   g_cur[NMAX];
__device__ int   g_col[EMAX];
__device__ int   g_blocksum[NBLK_SCAN + 1];

// ----------------------------------------------------------------------------
// degree / normalization
// ----------------------------------------------------------------------------
__global__ void zero_deg_kernel(int n) {
    int i = blockIdx.x * blockDim.x + threadIdx.x;
    if (i < n) g_deg[i] = 0;
}

__global__ void count_deg_kernel(const int* __restrict__ dst, int E) {
    int e = blockIdx.x * blockDim.x + threadIdx.x;
    if (e < E) atomicAdd(&g_deg[dst[e]], 1);
}

__global__ void compute_dis_kernel(int n) {
    int i = blockIdx.x * blockDim.x + threadIdx.x;
    if (i < n) g_dis[i] = rsqrtf((float)(g_deg[i] + 1));  // +1 = self loop
}

// ----------------------------------------------------------------------------
// multi-block exclusive scan of g_deg -> g_rowptr
// ----------------------------------------------------------------------------
__global__ __launch_bounds__(SCAN_B)
void scan_phase1_kernel(int n) {
    __shared__ int s[SCAN_B];
    int i = blockIdx.x * SCAN_B + threadIdx.x;
    int v = (i < n) ? g_deg[i] : 0;
    s[threadIdx.x] = v;
    __syncthreads();
#pragma unroll
    for (int off = 1; off < SCAN_B; off <<= 1) {
        int t = (threadIdx.x >= off) ? s[threadIdx.x - off] : 0;
        __syncthreads();
        s[threadIdx.x] += t;
        __syncthreads();
    }
    if (i < n) g_rowptr[i] = s[threadIdx.x] - v;
    if (threadIdx.x == SCAN_B - 1) g_blocksum[blockIdx.x] = s[SCAN_B - 1];
}

__global__ __launch_bounds__(64)
void scan_phase2_kernel(int nblk) {
    __shared__ int s[64];
    int v = (threadIdx.x < nblk) ? g_blocksum[threadIdx.x] : 0;
    s[threadIdx.x] = v;
    __syncthreads();
#pragma unroll
    for (int off = 1; off < 64; off <<= 1) {
        int t = (threadIdx.x >= off) ? s[threadIdx.x - off] : 0;
        __syncthreads();
        s[threadIdx.x] += t;
        __syncthreads();
    }
    if (threadIdx.x < nblk) g_blocksum[threadIdx.x] = s[threadIdx.x] - v;
    if (threadIdx.x == 63) g_blocksum[nblk] = s[63];
}

__global__ __launch_bounds__(SCAN_B)
void scan_phase3_kernel(int n, int nblk) {
    int i = blockIdx.x * SCAN_B + threadIdx.x;
    if (i < n) {
        int ex = g_rowptr[i] + g_blocksum[blockIdx.x];
        g_rowptr[i] = ex;
        g_cur[i] = ex;
    }
    if (i == 0) g_rowptr[n] = g_blocksum[nblk];
}

// ----------------------------------------------------------------------------
// CSR fill
// ----------------------------------------------------------------------------
__global__ void fill_csr_kernel(const int* __restrict__ src,
                                const int* __restrict__ dst, int E) {
    int e = blockIdx.x * blockDim.x + threadIdx.x;
    if (e < E) {
        int d = dst[e];
        int pos = atomicAdd(&g_cur[d], 1);
        g_col[pos] = src[e];
    }
}

// ----------------------------------------------------------------------------
// 3x-bf16 mma.sync GEMM (m16n8k16), hi/mid packed uint2 in smem:
//   C = A @ B   (no scaling — dis applied in aggregation)
// BM=128, BN=64, BK=16; 256 threads (8 warps, 4x2 warp grid, 32x32 per warp).
// C = Ah*Bh + Ah*Bm + Am*Bh, fp32 accum. Split: hi=bf16(x), mid=bf16(x-hi).
// ----------------------------------------------------------------------------
#define BM 128
#define BN 64
#define BK 16
#define ASTR 12
#define BSTR 68

__device__ __forceinline__ void split2(float f0, float f1, uint32_t& hi, uint32_t& mid) {
    __nv_bfloat16 h0 = __float2bfloat16(f0);
    __nv_bfloat16 h1 = __float2bfloat16(f1);
    float r0 = f0 - __bfloat162float(h0);
    float r1 = f1 - __bfloat162float(h1);
    __nv_bfloat162 hp = __nv_bfloat162(h0, h1);
    __nv_bfloat162 mp = __nv_bfloat162(__float2bfloat16(r0), __float2bfloat16(r1));
    hi  = *(uint32_t*)&hp;
    mid = *(uint32_t*)&mp;
}

__device__ __forceinline__ void mma_bf16(float* d, const uint32_t* a, const uint32_t* b) {
    asm volatile(
        "mma.sync.aligned.m16n8k16.row.col.f32.bf16.bf16.f32 "
        "{%0,%1,%2,%3}, {%4,%5,%6,%7}, {%8,%9}, {%0,%1,%2,%3};\n"
        : "+f"(d[0]), "+f"(d[1]), "+f"(d[2]), "+f"(d[3])
        : "r"(a[0]), "r"(a[1]), "r"(a[2]), "r"(a[3]),
          "r"(b[0]), "r"(b[1]));
}

__global__ __launch_bounds__(256)
void gemm_bf16_kernel(const float* __restrict__ A, const float* __restrict__ B,
                      float* __restrict__ C, int M, int N, int K) {
    __shared__ uint2 Ahl[BM][ASTR];     // 12 KB
    __shared__ uint2 Bhl[BK / 2][BSTR]; // 4.25 KB

    int tid  = threadIdx.x;
    int lane = tid & 31;
    int wid  = tid >> 5;
    int gID  = lane >> 2;
    int tig  = lane & 3;
    int warpM = wid >> 1;
    int warpN = wid & 1;

    int m0 = blockIdx.y * BM;
    int n0 = blockIdx.x * BN;

    int aRow = tid >> 1;
    int akk  = (tid & 1) * 8;
    int akp  = (tid & 1) * 4;
    int bkp  = (tid & 127) >> 4;
    int bn   = (tid & 15) * 4;

    float acc[2][4][4];
#pragma unroll
    for (int mt = 0; mt < 2; mt++)
#pragma unroll
        for (int nt = 0; nt < 4; nt++)
#pragma unroll
            for (int r = 0; r < 4; r++) acc[mt][nt][r] = 0.0f;

    int nC = K / BK;

    float4 pa0, pa1, pb0, pb1;
    {
        int gm = m0 + aRow;
        if (gm < M) {
            const float* ap = A + (size_t)gm * K + akk;
            pa0 = *(const float4*)(ap);
            pa1 = *(const float4*)(ap + 4);
        } else {
            pa0 = pa1 = make_float4(0.f, 0.f, 0.f, 0.f);
        }
        if (tid < 128) {
            const float* bp = B + (size_t)(2 * bkp) * N + n0 + bn;
            pb0 = *(const float4*)(bp);
            pb1 = *(const float4*)(bp + N);
        }
    }

    for (int c = 0; c < nC; c++) {
        {
            float va[8] = {pa0.x, pa0.y, pa0.z, pa0.w, pa1.x, pa1.y, pa1.z, pa1.w};
#pragma unroll
            for (int j = 0; j < 4; j++) {
                uint32_t hi, mid;
                split2(va[2 * j], va[2 * j + 1], hi, mid);
                Ahl[aRow][akp + j] = make_uint2(hi, mid);
            }
            if (tid < 128) {
                float b0[4] = {pb0.x, pb0.y, pb0.z, pb0.w};
                float b1[4] = {pb1.x, pb1.y, pb1.z, pb1.w};
#pragma unroll
                for (int j = 0; j < 4; j++) {
                    uint32_t hi, mid;
                    split2(b0[j], b1[j], hi, mid);
                    Bhl[bkp][bn + j] = make_uint2(hi, mid);
                }
            }
        }
        __syncthreads();

        if (c + 1 < nC) {
            int k0 = (c + 1) * BK;
            int gm = m0 + aRow;
            if (gm < M) {
                const float* ap = A + (size_t)gm * K + k0 + akk;
                pa0 = *(const float4*)(ap);
                pa1 = *(const float4*)(ap + 4);
            } else {
                pa0 = pa1 = make_float4(0.f, 0.f, 0.f, 0.f);
            }
            if (tid < 128) {
                const float* bp = B + (size_t)(k0 + 2 * bkp) * N + n0 + bn;
                pb0 = *(const float4*)(bp);
                pb1 = *(const float4*)(bp + N);
            }
        }

        {
            uint32_t ah[2][4], am[2][4];
#pragma unroll
            for (int mt = 0; mt < 2; mt++) {
                int r = warpM * 32 + mt * 16 + gID;
                uint2 q0 = Ahl[r][tig];
                uint2 q1 = Ahl[r + 8][tig];
                uint2 q2 = Ahl[r][tig + 4];
                uint2 q3 = Ahl[r + 8][tig + 4];
                ah[mt][0] = q0.x; am[mt][0] = q0.y;
                ah[mt][1] = q1.x; am[mt][1] = q1.y;
                ah[mt][2] = q2.x; am[mt][2] = q2.y;
                ah[mt][3] = q3.x; am[mt][3] = q3.y;
            }
            uint32_t bh[4][2], bm[4][2];
#pragma unroll
            for (int nt = 0; nt < 4; nt++) {
                int n = warpN * 32 + nt * 8 + gID;
                uint2 p0 = Bhl[tig][n];
                uint2 p1 = Bhl[tig + 4][n];
                bh[nt][0] = p0.x; bm[nt][0] = p0.y;
                bh[nt][1] = p1.x; bm[nt][1] = p1.y;
            }
#pragma unroll
            for (int mt = 0; mt < 2; mt++)
#pragma unroll
                for (int nt = 0; nt < 4; nt++) {
                    mma_bf16(acc[mt][nt], ah[mt], bh[nt]);
                    mma_bf16(acc[mt][nt], ah[mt], bm[nt]);
                    mma_bf16(acc[mt][nt], am[mt], bh[nt]);
                }
        }
        __syncthreads();
    }

    // ---- epilogue: plain store (no dis scale) ----
#pragma unroll
    for (int mt = 0; mt < 2; mt++) {
        int row0 = m0 + warpM * 32 + mt * 16 + gID;
        int row1 = row0 + 8;
#pragma unroll
        for (int nt = 0; nt < 4; nt++) {
            int col = n0 + warpN * 32 + nt * 8 + tig * 2;
            if (row0 < M) {
                float2 v = {acc[mt][nt][0], acc[mt][nt][1]};
                *(float2*)(C + (size_t)row0 * N + col) = v;
            }
            if (row1 < M) {
                float2 v = {acc[mt][nt][2], acc[mt][nt][3]};
                *(float2*)(C + (size_t)row1 * N + col) = v;
            }
        }
    }
}

// ----------------------------------------------------------------------------
// pull aggregation (dis applied inline) + bias + exact GELU
// Out[d,:] = gelu( dis[d] * ( dis[d]*H[d,:] + sum_s dis[s]*H[s,:] ) + bias )
// ----------------------------------------------------------------------------
__device__ __forceinline__ float4 f4fma(float4 a, float4 h, float w) {
    return make_float4(fmaf(h.x, w, a.x), fmaf(h.y, w, a.y),
                       fmaf(h.z, w, a.z), fmaf(h.w, w, a.w));
}

template <int TPG>
__global__ __launch_bounds__(256)
void agg_gelu_kernel(const float* __restrict__ H, const float* __restrict__ bias,
                     float* __restrict__ Out, int n) {
    int gid = (int)(blockIdx.x * blockDim.x + threadIdx.x) / TPG;
    int t   = threadIdx.x & (TPG - 1);
    if (gid >= n) return;

    const float4* H4 = (const float4*)H;
    int beg = g_rowptr[gid];
    int end = g_rowptr[gid + 1];

    float dd = g_dis[gid];
    float4 z  = make_float4(0.f, 0.f, 0.f, 0.f);
    float4 a0 = f4fma(z, H4[(size_t)gid * TPG + t], dd);   // self-loop
    float4 a1 = z, a2 = z, a3 = z;

    int p = beg;
    for (; p + 3 < end; p += 4) {
        int s0 = g_col[p];
        int s1 = g_col[p + 1];
        int s2 = g_col[p + 2];
        int s3 = g_col[p + 3];
        float w0 = g_dis[s0];
        float w1 = g_dis[s1];
        float w2 = g_dis[s2];
        float w3 = g_dis[s3];
        a0 = f4fma(a0, H4[(size_t)s0 * TPG + t], w0);
        a1 = f4fma(a1, H4[(size_t)s1 * TPG + t], w1);
        a2 = f4fma(a2, H4[(size_t)s2 * TPG + t], w2);
        a3 = f4fma(a3, H4[(size_t)s3 * TPG + t], w3);
    }
    for (; p < end; p++) {
        int s0 = g_col[p];
        a0 = f4fma(a0, H4[(size_t)s0 * TPG + t], g_dis[s0]);
    }

    float4 acc = make_float4(a0.x + a1.x + a2.x + a3.x,
                             a0.y + a1.y + a2.y + a3.y,
                             a0.z + a1.z + a2.z + a3.z,
                             a0.w + a1.w + a2.w + a3.w);
    float4 bb = ((const float4*)bias)[t];

    float x0 = acc.x * dd + bb.x;
    float x1 = acc.y * dd + bb.y;
    float x2 = acc.z * dd + bb.z;
    float x3 = acc.w * dd + bb.w;
    const float inv_sqrt2 = 0.70710678118654752f;
    float4 o;
    o.x = 0.5f * x0 * (1.0f + erff(x0 * inv_sqrt2));
    o.y = 0.5f * x1 * (1.0f + erff(x1 * inv_sqrt2));
    o.z = 0.5f * x2 * (1.0f + erff(x2 * inv_sqrt2));
    o.w = 0.5f * x3 * (1.0f + erff(x3 * inv_sqrt2));
    ((float4*)Out)[(size_t)gid * TPG + t] = o;
}

// ----------------------------------------------------------------------------
extern "C" void kernel_launch(void* const* d_in, const int* in_sizes, int n_in,
                              void* d_out, int out_size) {
    const float* node_emb = (const float*)d_in[0];   // [N, 256]
    const float* W1       = (const float*)d_in[1];   // [256, 256]
    const float* b1       = (const float*)d_in[2];   // [256]
    const float* W2       = (const float*)d_in[3];   // [256, 128]
    const float* b2       = (const float*)d_in[4];   // [128]
    const int*   eidx     = (const int*)d_in[5];     // [2, E]

    int N = in_sizes[0] / EMB;
    int E = in_sizes[5] / 2;
    const int* src = eidx;
    const int* dst = eidx + E;

    float* H1 = nullptr; float* A1 = nullptr; float* H2 = nullptr;
    cudaGetSymbolAddress((void**)&H1, g_H1);
    cudaGetSymbolAddress((void**)&A1, g_A1);
    cudaGetSymbolAddress((void**)&H2, g_H2);
    float* outp = (float*)d_out;

    // one-time side stream + events (deterministic; no device memory)
    static cudaStream_t sB = nullptr;
    static cudaEvent_t evFork = nullptr, evCsr = nullptr;
    if (sB == nullptr) {
        cudaStreamCreateWithFlags(&sB, cudaStreamNonBlocking);
        cudaEventCreateWithFlags(&evFork, cudaEventDisableTiming);
        cudaEventCreateWithFlags(&evCsr, cudaEventDisableTiming);
    }

    int nblk_scan = (N + SCAN_B - 1) / SCAN_B;

    // ---- fork: CSR/degree pipeline on side stream, GEMM1 on main ----
    cudaEventRecord(evFork, 0);
    cudaStreamWaitEvent(sB, evFork, 0);

    zero_deg_kernel<<<(N + 255) / 256, 256, 0, sB>>>(N);
    count_deg_kernel<<<(E + 255) / 256, 256, 0, sB>>>(dst, E);
    compute_dis_kernel<<<(N + 255) / 256, 256, 0, sB>>>(N);
    scan_phase1_kernel<<<nblk_scan, SCAN_B, 0, sB>>>(N);
    scan_phase2_kernel<<<1, 64, 0, sB>>>(nblk_scan);
    scan_phase3_kernel<<<nblk_scan, SCAN_B, 0, sB>>>(N, nblk_scan);
    fill_csr_kernel<<<(E + 255) / 256, 256, 0, sB>>>(src, dst, E);
    cudaEventRecord(evCsr, sB);

    // ---- layer 1 GEMM (independent of CSR) ----
    {
        dim3 grid(MID / BN, (N + BM - 1) / BM);
        gemm_bf16_kernel<<<grid, 256>>>(node_emb, W1, H1, N, MID, EMB);
    }

    // join: aggregation needs rowptr/col/dis
    cudaStreamWaitEvent(0, evCsr, 0);
    {
        const int TPG = MID / 4;   // 64
        int groups_per_blk = 256 / TPG;
        int nblk = (N + groups_per_blk - 1) / groups_per_blk;
        agg_gelu_kernel<TPG><<<nblk, 256>>>(H1, b1, A1, N);
    }

    // ---- layer 2 ----
    {
        dim3 grid(OUTD / BN, (N + BM - 1) / BM);
        gemm_bf16_kernel<<<grid, 256>>>(A1, W2, H2, N, OUTD, MID);
    }
    {
        const int TPG = OUTD / 4;  // 32
        int groups_per_blk = 256 / TPG;
        int nblk = (N + groups_per_blk - 1) / groups_per_blk;
        agg_gelu_kernel<TPG><<<nblk, 256>>>(H2, b2, outp, N);
    }
}

// round 13
// speedup vs baseline: 1.0985x; 1.0617x over previous
#include <cuda_runtime.h>
#include <cuda_bf16.h>
#include <math.h>
#include <stdint.h>

#define NMAX   50000
#define EMAX   1048576
#define EMB    256
#define MID    256
#define OUTD   128
#define SCAN_B 1024
#define NBLK_SCAN ((NMAX + SCAN_B - 1) / SCAN_B)   // 49

// ---- scratch (static device globals; no runtime allocation) ----
__device__ float g_H1[NMAX * MID];     // dis .* (node_emb @ W1)
__device__ float g_A1[NMAX * MID];     // gelu(agg) -> layer-2 input
__device__ float g_H2[NMAX * OUTD];    // dis .* (X1 @ W2)
__device__ float g_dis[NMAX];          // D^-1/2 (in-degree + self loop)
__device__ int   g_deg[NMAX];
__device__ int   g_rowptr[NMAX + 1];
__device__ int   g_cur[NMAX];
__device__ int   g_col[EMAX];
__device__ int   g_blocksum[NBLK_SCAN + 1];

// ----------------------------------------------------------------------------
// degree / normalization
// ----------------------------------------------------------------------------
__global__ void zero_deg_kernel(int n) {
    int i = blockIdx.x * blockDim.x + threadIdx.x;
    if (i < n) g_deg[i] = 0;
}

__global__ void count_deg_kernel(const int* __restrict__ dst, int E) {
    int e = blockIdx.x * blockDim.x + threadIdx.x;
    if (e < E) atomicAdd(&g_deg[dst[e]], 1);
}

__global__ void compute_dis_kernel(int n) {
    int i = blockIdx.x * blockDim.x + threadIdx.x;
    if (i < n) g_dis[i] = rsqrtf((float)(g_deg[i] + 1));  // +1 = self loop
}

// ----------------------------------------------------------------------------
// multi-block exclusive scan of g_deg -> g_rowptr
// ----------------------------------------------------------------------------
__global__ __launch_bounds__(SCAN_B)
void scan_phase1_kernel(int n) {
    __shared__ int s[SCAN_B];
    int i = blockIdx.x * SCAN_B + threadIdx.x;
    int v = (i < n) ? g_deg[i] : 0;
    s[threadIdx.x] = v;
    __syncthreads();
#pragma unroll
    for (int off = 1; off < SCAN_B; off <<= 1) {
        int t = (threadIdx.x >= off) ? s[threadIdx.x - off] : 0;
        __syncthreads();
        s[threadIdx.x] += t;
        __syncthreads();
    }
    if (i < n) g_rowptr[i] = s[threadIdx.x] - v;
    if (threadIdx.x == SCAN_B - 1) g_blocksum[blockIdx.x] = s[SCAN_B - 1];
}

__global__ __launch_bounds__(64)
void scan_phase2_kernel(int nblk) {
    __shared__ int s[64];
    int v = (threadIdx.x < nblk) ? g_blocksum[threadIdx.x] : 0;
    s[threadIdx.x] = v;
    __syncthreads();
#pragma unroll
    for (int off = 1; off < 64; off <<= 1) {
        int t = (threadIdx.x >= off) ? s[threadIdx.x - off] : 0;
        __syncthreads();
        s[threadIdx.x] += t;
        __syncthreads();
    }
    if (threadIdx.x < nblk) g_blocksum[threadIdx.x] = s[threadIdx.x] - v;
    if (threadIdx.x == 63) g_blocksum[nblk] = s[63];
}

__global__ __launch_bounds__(SCAN_B)
void scan_phase3_kernel(int n, int nblk) {
    int i = blockIdx.x * SCAN_B + threadIdx.x;
    if (i < n) {
        int ex = g_rowptr[i] + g_blocksum[blockIdx.x];
        g_rowptr[i] = ex;
        g_cur[i] = ex;
    }
    if (i == 0) g_rowptr[n] = g_blocksum[nblk];
}

// ----------------------------------------------------------------------------
// CSR fill
// ----------------------------------------------------------------------------
__global__ void fill_csr_kernel(const int* __restrict__ src,
                                const int* __restrict__ dst, int E) {
    int e = blockIdx.x * blockDim.x + threadIdx.x;
    if (e < E) {
        int d = dst[e];
        int pos = atomicAdd(&g_cur[d], 1);
        g_col[pos] = src[e];
    }
}

// ----------------------------------------------------------------------------
// 3x-bf16 mma.sync GEMM (m16n8k16), hi/mid packed uint2 in smem:
//   C[m,:] = dis[m] * (A @ B)[m,:]
// BM=128, BN=64, BK=16; 256 threads (8 warps, 4x2 warp grid, 32x32 per warp).
// C = Ah*Bh + Ah*Bm + Am*Bh, fp32 accum. Split: hi=bf16(x), mid=bf16(x-hi).
// (R9 known-good kernel, verbatim)
// ----------------------------------------------------------------------------
#define BM 128
#define BN 64
#define BK 16
#define ASTR 12
#define BSTR 68

__device__ __forceinline__ void split2(float f0, float f1, uint32_t& hi, uint32_t& mid) {
    __nv_bfloat16 h0 = __float2bfloat16(f0);
    __nv_bfloat16 h1 = __float2bfloat16(f1);
    float r0 = f0 - __bfloat162float(h0);
    float r1 = f1 - __bfloat162float(h1);
    __nv_bfloat162 hp = __nv_bfloat162(h0, h1);
    __nv_bfloat162 mp = __nv_bfloat162(__float2bfloat16(r0), __float2bfloat16(r1));
    hi  = *(uint32_t*)&hp;
    mid = *(uint32_t*)&mp;
}

__device__ __forceinline__ void mma_bf16(float* d, const uint32_t* a, const uint32_t* b) {
    asm volatile(
        "mma.sync.aligned.m16n8k16.row.col.f32.bf16.bf16.f32 "
        "{%0,%1,%2,%3}, {%4,%5,%6,%7}, {%8,%9}, {%0,%1,%2,%3};\n"
        : "+f"(d[0]), "+f"(d[1]), "+f"(d[2]), "+f"(d[3])
        : "r"(a[0]), "r"(a[1]), "r"(a[2]), "r"(a[3]),
          "r"(b[0]), "r"(b[1]));
}

__global__ __launch_bounds__(256)
void gemm_bf16_scale_kernel(const float* __restrict__ A, const float* __restrict__ B,
                            float* __restrict__ C, int M, int N, int K) {
    __shared__ uint2 Ahl[BM][ASTR];     // 12 KB
    __shared__ uint2 Bhl[BK / 2][BSTR]; // 4.25 KB

    int tid  = threadIdx.x;
    int lane = tid & 31;
    int wid  = tid >> 5;
    int gID  = lane >> 2;
    int tig  = lane & 3;
    int warpM = wid >> 1;
    int warpN = wid & 1;

    int m0 = blockIdx.y * BM;
    int n0 = blockIdx.x * BN;

    int aRow = tid >> 1;
    int akk  = (tid & 1) * 8;
    int akp  = (tid & 1) * 4;
    int bkp  = (tid & 127) >> 4;
    int bn   = (tid & 15) * 4;

    float acc[2][4][4];
#pragma unroll
    for (int mt = 0; mt < 2; mt++)
#pragma unroll
        for (int nt = 0; nt < 4; nt++)
#pragma unroll
            for (int r = 0; r < 4; r++) acc[mt][nt][r] = 0.0f;

    int nC = K / BK;

    float4 pa0, pa1, pb0, pb1;
    {
        int gm = m0 + aRow;
        if (gm < M) {
            const float* ap = A + (size_t)gm * K + akk;
            pa0 = *(const float4*)(ap);
            pa1 = *(const float4*)(ap + 4);
        } else {
            pa0 = pa1 = make_float4(0.f, 0.f, 0.f, 0.f);
        }
        if (tid < 128) {
            const float* bp = B + (size_t)(2 * bkp) * N + n0 + bn;
            pb0 = *(const float4*)(bp);
            pb1 = *(const float4*)(bp + N);
        }
    }

    for (int c = 0; c < nC; c++) {
        {
            float va[8] = {pa0.x, pa0.y, pa0.z, pa0.w, pa1.x, pa1.y, pa1.z, pa1.w};
#pragma unroll
            for (int j = 0; j < 4; j++) {
                uint32_t hi, mid;
                split2(va[2 * j], va[2 * j + 1], hi, mid);
                Ahl[aRow][akp + j] = make_uint2(hi, mid);
            }
            if (tid < 128) {
                float b0[4] = {pb0.x, pb0.y, pb0.z, pb0.w};
                float b1[4] = {pb1.x, pb1.y, pb1.z, pb1.w};
#pragma unroll
                for (int j = 0; j < 4; j++) {
                    uint32_t hi, mid;
                    split2(b0[j], b1[j], hi, mid);
                    Bhl[bkp][bn + j] = make_uint2(hi, mid);
                }
            }
        }
        __syncthreads();

        if (c + 1 < nC) {
            int k0 = (c + 1) * BK;
            int gm = m0 + aRow;
            if (gm < M) {
                const float* ap = A + (size_t)gm * K + k0 + akk;
                pa0 = *(const float4*)(ap);
                pa1 = *(const float4*)(ap + 4);
            } else {
                pa0 = pa1 = make_float4(0.f, 0.f, 0.f, 0.f);
            }
            if (tid < 128) {
                const float* bp = B + (size_t)(k0 + 2 * bkp) * N + n0 + bn;
                pb0 = *(const float4*)(bp);
                pb1 = *(const float4*)(bp + N);
            }
        }

        {
            uint32_t ah[2][4], am[2][4];
#pragma unroll
            for (int mt = 0; mt < 2; mt++) {
                int r = warpM * 32 + mt * 16 + gID;
                uint2 q0 = Ahl[r][tig];
                uint2 q1 = Ahl[r + 8][tig];
                uint2 q2 = Ahl[r][tig + 4];
                uint2 q3 = Ahl[r + 8][tig + 4];
                ah[mt][0] = q0.x; am[mt][0] = q0.y;
                ah[mt][1] = q1.x; am[mt][1] = q1.y;
                ah[mt][2] = q2.x; am[mt][2] = q2.y;
                ah[mt][3] = q3.x; am[mt][3] = q3.y;
            }
            uint32_t bh[4][2], bm[4][2];
#pragma unroll
            for (int nt = 0; nt < 4; nt++) {
                int n = warpN * 32 + nt * 8 + gID;
                uint2 p0 = Bhl[tig][n];
                uint2 p1 = Bhl[tig + 4][n];
                bh[nt][0] = p0.x; bm[nt][0] = p0.y;
                bh[nt][1] = p1.x; bm[nt][1] = p1.y;
            }
#pragma unroll
            for (int mt = 0; mt < 2; mt++)
#pragma unroll
                for (int nt = 0; nt < 4; nt++) {
                    mma_bf16(acc[mt][nt], ah[mt], bh[nt]);
                    mma_bf16(acc[mt][nt], ah[mt], bm[nt]);
                    mma_bf16(acc[mt][nt], am[mt], bh[nt]);
                }
        }
        __syncthreads();
    }

    // ---- epilogue: scale by dis[row], store ----
#pragma unroll
    for (int mt = 0; mt < 2; mt++) {
        int row0 = m0 + warpM * 32 + mt * 16 + gID;
        int row1 = row0 + 8;
        float s0 = (row0 < M) ? g_dis[row0] : 0.0f;
        float s1 = (row1 < M) ? g_dis[row1] : 0.0f;
#pragma unroll
        for (int nt = 0; nt < 4; nt++) {
            int col = n0 + warpN * 32 + nt * 8 + tig * 2;
            if (row0 < M) {
                float2 v = {acc[mt][nt][0] * s0, acc[mt][nt][1] * s0};
                *(float2*)(C + (size_t)row0 * N + col) = v;
            }
            if (row1 < M) {
                float2 v = {acc[mt][nt][2] * s1, acc[mt][nt][3] * s1};
                *(float2*)(C + (size_t)row1 * N + col) = v;
            }
        }
    }
}

// ----------------------------------------------------------------------------
// pull aggregation + bias + exact GELU (R9 verbatim)
// Out[d,:] = gelu( dis[d] * (Hs[d,:] + sum_{s in N(d)} Hs[s,:]) + bias )
// ----------------------------------------------------------------------------
__device__ __forceinline__ float4 f4add(float4 a, float4 b) {
    return make_float4(a.x + b.x, a.y + b.y, a.z + b.z, a.w + b.w);
}

template <int TPG>
__global__ __launch_bounds__(256)
void agg_gelu_kernel(const float* __restrict__ Hs, const float* __restrict__ bias,
                     float* __restrict__ Out, int n) {
    int gid = (int)(blockIdx.x * blockDim.x + threadIdx.x) / TPG;
    int t   = threadIdx.x & (TPG - 1);
    if (gid >= n) return;

    const float4* H4 = (const float4*)Hs;
    int beg = g_rowptr[gid];
    int end = g_rowptr[gid + 1];

    float4 a0 = H4[(size_t)gid * TPG + t];
    float4 a1 = make_float4(0.f, 0.f, 0.f, 0.f);
    float4 a2 = a1, a3 = a1;

    int p = beg;
    for (; p + 3 < end; p += 4) {
        int s0 = g_col[p];
        int s1 = g_col[p + 1];
        int s2 = g_col[p + 2];
        int s3 = g_col[p + 3];
        a0 = f4add(a0, H4[(size_t)s0 * TPG + t]);
        a1 = f4add(a1, H4[(size_t)s1 * TPG + t]);
        a2 = f4add(a2, H4[(size_t)s2 * TPG + t]);
        a3 = f4add(a3, H4[(size_t)s3 * TPG + t]);
    }
    for (; p < end; p++)
        a0 = f4add(a0, H4[(size_t)g_col[p] * TPG + t]);

    float4 acc = f4add(f4add(a0, a1), f4add(a2, a3));
    float dd = g_dis[gid];
    float4 bb = ((const float4*)bias)[t];

    float x0 = acc.x * dd + bb.x;
    float x1 = acc.y * dd + bb.y;
    float x2 = acc.z * dd + bb.z;
    float x3 = acc.w * dd + bb.w;
    const float inv_sqrt2 = 0.70710678118654752f;
    float4 o;
    o.x = 0.5f * x0 * (1.0f + erff(x0 * inv_sqrt2));
    o.y = 0.5f * x1 * (1.0f + erff(x1 * inv_sqrt2));
    o.z = 0.5f * x2 * (1.0f + erff(x2 * inv_sqrt2));
    o.w = 0.5f * x3 * (1.0f + erff(x3 * inv_sqrt2));
    ((float4*)Out)[(size_t)gid * TPG + t] = o;
}

// ----------------------------------------------------------------------------
extern "C" void kernel_launch(void* const* d_in, const int* in_sizes, int n_in,
                              void* d_out, int out_size) {
    const float* node_emb = (const float*)d_in[0];   // [N, 256]
    const float* W1       = (const float*)d_in[1];   // [256, 256]
    const float* b1       = (const float*)d_in[2];   // [256]
    const float* W2       = (const float*)d_in[3];   // [256, 128]
    const float* b2       = (const float*)d_in[4];   // [128]
    const int*   eidx     = (const int*)d_in[5];     // [2, E]

    int N = in_sizes[0] / EMB;
    int E = in_sizes[5] / 2;
    const int* src = eidx;
    const int* dst = eidx + E;

    float* H1 = nullptr; float* A1 = nullptr; float* H2 = nullptr;
    cudaGetSymbolAddress((void**)&H1, g_H1);
    cudaGetSymbolAddress((void**)&A1, g_A1);
    cudaGetSymbolAddress((void**)&H2, g_H2);
    float* outp = (float*)d_out;

    // one-time side stream + events (deterministic; no device memory)
    static cudaStream_t sB = nullptr;
    static cudaEvent_t evFork = nullptr, evCsr = nullptr;
    if (sB == nullptr) {
        cudaStreamCreateWithFlags(&sB, cudaStreamNonBlocking);
        cudaEventCreateWithFlags(&evFork, cudaEventDisableTiming);
        cudaEventCreateWithFlags(&evCsr, cudaEventDisableTiming);
    }

    int nblk_scan = (N + SCAN_B - 1) / SCAN_B;

    // ---- degrees + dis on MAIN stream (GEMM1 epilogue needs g_dis) ----
    zero_deg_kernel<<<(N + 255) / 256, 256>>>(N);
    count_deg_kernel<<<(E + 255) / 256, 256>>>(dst, E);
    compute_dis_kernel<<<(N + 255) / 256, 256>>>(N);

    // ---- fork: scan + CSR fill on side stream, hidden under GEMM1 ----
    cudaEventRecord(evFork, 0);
    cudaStreamWaitEvent(sB, evFork, 0);
    scan_phase1_kernel<<<nblk_scan, SCAN_B, 0, sB>>>(N);
    scan_phase2_kernel<<<1, 64, 0, sB>>>(nblk_scan);
    scan_phase3_kernel<<<nblk_scan, SCAN_B, 0, sB>>>(N, nblk_scan);
    fill_csr_kernel<<<(E + 255) / 256, 256, 0, sB>>>(src, dst, E);
    cudaEventRecord(evCsr, sB);

    // ---- layer 1 GEMM (concurrent with scan/fill) ----
    {
        dim3 grid(MID / BN, (N + BM - 1) / BM);
        gemm_bf16_scale_kernel<<<grid, 256>>>(node_emb, W1, H1, N, MID, EMB);
    }

    // join: aggregation needs rowptr/col
    cudaStreamWaitEvent(0, evCsr, 0);
    {
        const int TPG = MID / 4;   // 64
        int groups_per_blk = 256 / TPG;
        int nblk = (N + groups_per_blk - 1) / groups_per_blk;
        agg_gelu_kernel<TPG><<<nblk, 256>>>(H1, b1, A1, N);
    }

    // ---- layer 2 ----
    {
        dim3 grid(OUTD / BN, (N + BM - 1) / BM);
        gemm_bf16_scale_kernel<<<grid, 256>>>(A1, W2, H2, N, OUTD, MID);
    }
    {
        const int TPG = OUTD / 4;  // 32
        int groups_per_blk = 256 / TPG;
        int nblk = (N + groups_per_blk - 1) / groups_per_blk;
        agg_gelu_kernel<TPG><<<nblk, 256>>>(H2, b2, outp, N);
    }
}

// round 14
// speedup vs baseline: 1.1637x; 1.0594x over previous
#include <cuda_runtime.h>
#include <cuda_bf16.h>
#include <cuda_fp16.h>
#include <math.h>
#include <stdint.h>

#define NMAX   50000
#define EMAX   1048576
#define EMB    256
#define MID    256
#define OUTD   128
#define SCAN_B 1024
#define NBLK_SCAN ((NMAX + SCAN_B - 1) / SCAN_B)   // 49

// ---- scratch (static device globals; no runtime allocation) ----
__device__ __half g_H1h[NMAX * MID];   // dis .* (node_emb @ W1), fp16
__device__ float  g_A1[NMAX * MID];    // gelu(agg) -> layer-2 input
__device__ float  g_H2[NMAX * OUTD];   // dis .* (X1 @ W2), fp32
__device__ float  g_dis[NMAX];         // D^-1/2 (in-degree + self loop)
__device__ int    g_deg[NMAX];
__device__ int    g_rowptr[NMAX + 1];
__device__ int    g_cur[NMAX];
__device__ int    g_col[EMAX];
__device__ int    g_blocksum[NBLK_SCAN + 1];

// ----------------------------------------------------------------------------
// degree / normalization
// ----------------------------------------------------------------------------
__global__ void zero_deg_kernel(int n) {
    int i = blockIdx.x * blockDim.x + threadIdx.x;
    if (i < n) g_deg[i] = 0;
}

__global__ void count_deg_kernel(const int* __restrict__ dst, int E) {
    int e = blockIdx.x * blockDim.x + threadIdx.x;
    if (e < E) atomicAdd(&g_deg[dst[e]], 1);
}

__global__ void compute_dis_kernel(int n) {
    int i = blockIdx.x * blockDim.x + threadIdx.x;
    if (i < n) g_dis[i] = rsqrtf((float)(g_deg[i] + 1));  // +1 = self loop
}

// ----------------------------------------------------------------------------
// multi-block exclusive scan of g_deg -> g_rowptr
// ----------------------------------------------------------------------------
__global__ __launch_bounds__(SCAN_B)
void scan_phase1_kernel(int n) {
    __shared__ int s[SCAN_B];
    int i = blockIdx.x * SCAN_B + threadIdx.x;
    int v = (i < n) ? g_deg[i] : 0;
    s[threadIdx.x] = v;
    __syncthreads();
#pragma unroll
    for (int off = 1; off < SCAN_B; off <<= 1) {
        int t = (threadIdx.x >= off) ? s[threadIdx.x - off] : 0;
        __syncthreads();
        s[threadIdx.x] += t;
        __syncthreads();
    }
    if (i < n) g_rowptr[i] = s[threadIdx.x] - v;
    if (threadIdx.x == SCAN_B - 1) g_blocksum[blockIdx.x] = s[SCAN_B - 1];
}

__global__ __launch_bounds__(64)
void scan_phase2_kernel(int nblk) {
    __shared__ int s[64];
    int v = (threadIdx.x < nblk) ? g_blocksum[threadIdx.x] : 0;
    s[threadIdx.x] = v;
    __syncthreads();
#pragma unroll
    for (int off = 1; off < 64; off <<= 1) {
        int t = (threadIdx.x >= off) ? s[threadIdx.x - off] : 0;
        __syncthreads();
        s[threadIdx.x] += t;
        __syncthreads();
    }
    if (threadIdx.x < nblk) g_blocksum[threadIdx.x] = s[threadIdx.x] - v;
    if (threadIdx.x == 63) g_blocksum[nblk] = s[63];
}

__global__ __launch_bounds__(SCAN_B)
void scan_phase3_kernel(int n, int nblk) {
    int i = blockIdx.x * SCAN_B + threadIdx.x;
    if (i < n) {
        int ex = g_rowptr[i] + g_blocksum[blockIdx.x];
        g_rowptr[i] = ex;
        g_cur[i] = ex;
    }
    if (i == 0) g_rowptr[n] = g_blocksum[nblk];
}

// ----------------------------------------------------------------------------
// CSR fill
// ----------------------------------------------------------------------------
__global__ void fill_csr_kernel(const int* __restrict__ src,
                                const int* __restrict__ dst, int E) {
    int e = blockIdx.x * blockDim.x + threadIdx.x;
    if (e < E) {
        int d = dst[e];
        int pos = atomicAdd(&g_cur[d], 1);
        g_col[pos] = src[e];
    }
}

// ----------------------------------------------------------------------------
// 3x-bf16 mma.sync GEMM (m16n8k16), hi/mid packed uint2 in smem:
//   C[m,:] = dis[m] * (A @ B)[m,:]
// BM=128, BN=64, BK=16; 256 threads (8 warps, 4x2 warp grid, 32x32 per warp).
// HOUT=true: store fp16 (__half2); HOUT=false: store fp32.
// ----------------------------------------------------------------------------
#define BM 128
#define BN 64
#define BK 16
#define ASTR 12
#define BSTR 68

__device__ __forceinline__ void split2(float f0, float f1, uint32_t& hi, uint32_t& mid) {
    __nv_bfloat16 h0 = __float2bfloat16(f0);
    __nv_bfloat16 h1 = __float2bfloat16(f1);
    float r0 = f0 - __bfloat162float(h0);
    float r1 = f1 - __bfloat162float(h1);
    __nv_bfloat162 hp = __nv_bfloat162(h0, h1);
    __nv_bfloat162 mp = __nv_bfloat162(__float2bfloat16(r0), __float2bfloat16(r1));
    hi  = *(uint32_t*)&hp;
    mid = *(uint32_t*)&mp;
}

__device__ __forceinline__ void mma_bf16(float* d, const uint32_t* a, const uint32_t* b) {
    asm volatile(
        "mma.sync.aligned.m16n8k16.row.col.f32.bf16.bf16.f32 "
        "{%0,%1,%2,%3}, {%4,%5,%6,%7}, {%8,%9}, {%0,%1,%2,%3};\n"
        : "+f"(d[0]), "+f"(d[1]), "+f"(d[2]), "+f"(d[3])
        : "r"(a[0]), "r"(a[1]), "r"(a[2]), "r"(a[3]),
          "r"(b[0]), "r"(b[1]));
}

template <bool HOUT>
__global__ __launch_bounds__(256)
void gemm_bf16_scale_kernel(const float* __restrict__ A, const float* __restrict__ B,
                            void* __restrict__ Cv, int M, int N, int K) {
    __shared__ uint2 Ahl[BM][ASTR];     // 12 KB
    __shared__ uint2 Bhl[BK / 2][BSTR]; // 4.25 KB

    int tid  = threadIdx.x;
    int lane = tid & 31;
    int wid  = tid >> 5;
    int gID  = lane >> 2;
    int tig  = lane & 3;
    int warpM = wid >> 1;
    int warpN = wid & 1;

    int m0 = blockIdx.y * BM;
    int n0 = blockIdx.x * BN;

    int aRow = tid >> 1;
    int akk  = (tid & 1) * 8;
    int akp  = (tid & 1) * 4;
    int bkp  = (tid & 127) >> 4;
    int bn   = (tid & 15) * 4;

    float acc[2][4][4];
#pragma unroll
    for (int mt = 0; mt < 2; mt++)
#pragma unroll
        for (int nt = 0; nt < 4; nt++)
#pragma unroll
            for (int r = 0; r < 4; r++) acc[mt][nt][r] = 0.0f;

    int nC = K / BK;

    float4 pa0, pa1, pb0, pb1;
    {
        int gm = m0 + aRow;
        if (gm < M) {
            const float* ap = A + (size_t)gm * K + akk;
            pa0 = *(const float4*)(ap);
            pa1 = *(const float4*)(ap + 4);
        } else {
            pa0 = pa1 = make_float4(0.f, 0.f, 0.f, 0.f);
        }
        if (tid < 128) {
            const float* bp = B + (size_t)(2 * bkp) * N + n0 + bn;
            pb0 = *(const float4*)(bp);
            pb1 = *(const float4*)(bp + N);
        }
    }

    for (int c = 0; c < nC; c++) {
        {
            float va[8] = {pa0.x, pa0.y, pa0.z, pa0.w, pa1.x, pa1.y, pa1.z, pa1.w};
#pragma unroll
            for (int j = 0; j < 4; j++) {
                uint32_t hi, mid;
                split2(va[2 * j], va[2 * j + 1], hi, mid);
                Ahl[aRow][akp + j] = make_uint2(hi, mid);
            }
            if (tid < 128) {
                float b0[4] = {pb0.x, pb0.y, pb0.z, pb0.w};
                float b1[4] = {pb1.x, pb1.y, pb1.z, pb1.w};
#pragma unroll
                for (int j = 0; j < 4; j++) {
                    uint32_t hi, mid;
                    split2(b0[j], b1[j], hi, mid);
                    Bhl[bkp][bn + j] = make_uint2(hi, mid);
                }
            }
        }
        __syncthreads();

        if (c + 1 < nC) {
            int k0 = (c + 1) * BK;
            int gm = m0 + aRow;
            if (gm < M) {
                const float* ap = A + (size_t)gm * K + k0 + akk;
                pa0 = *(const float4*)(ap);
                pa1 = *(const float4*)(ap + 4);
            } else {
                pa0 = pa1 = make_float4(0.f, 0.f, 0.f, 0.f);
            }
            if (tid < 128) {
                const float* bp = B + (size_t)(k0 + 2 * bkp) * N + n0 + bn;
                pb0 = *(const float4*)(bp);
                pb1 = *(const float4*)(bp + N);
            }
        }

        {
            uint32_t ah[2][4], am[2][4];
#pragma unroll
            for (int mt = 0; mt < 2; mt++) {
                int r = warpM * 32 + mt * 16 + gID;
                uint2 q0 = Ahl[r][tig];
                uint2 q1 = Ahl[r + 8][tig];
                uint2 q2 = Ahl[r][tig + 4];
                uint2 q3 = Ahl[r + 8][tig + 4];
                ah[mt][0] = q0.x; am[mt][0] = q0.y;
                ah[mt][1] = q1.x; am[mt][1] = q1.y;
                ah[mt][2] = q2.x; am[mt][2] = q2.y;
                ah[mt][3] = q3.x; am[mt][3] = q3.y;
            }
            uint32_t bh[4][2], bm[4][2];
#pragma unroll
            for (int nt = 0; nt < 4; nt++) {
                int n = warpN * 32 + nt * 8 + gID;
                uint2 p0 = Bhl[tig][n];
                uint2 p1 = Bhl[tig + 4][n];
                bh[nt][0] = p0.x; bm[nt][0] = p0.y;
                bh[nt][1] = p1.x; bm[nt][1] = p1.y;
            }
#pragma unroll
            for (int mt = 0; mt < 2; mt++)
#pragma unroll
                for (int nt = 0; nt < 4; nt++) {
                    mma_bf16(acc[mt][nt], ah[mt], bh[nt]);
                    mma_bf16(acc[mt][nt], ah[mt], bm[nt]);
                    mma_bf16(acc[mt][nt], am[mt], bh[nt]);
                }
        }
        __syncthreads();
    }

    // ---- epilogue: scale by dis[row], store (fp16 or fp32) ----
#pragma unroll
    for (int mt = 0; mt < 2; mt++) {
        int row0 = m0 + warpM * 32 + mt * 16 + gID;
        int row1 = row0 + 8;
        float s0 = (row0 < M) ? g_dis[row0] : 0.0f;
        float s1 = (row1 < M) ? g_dis[row1] : 0.0f;
#pragma unroll
        for (int nt = 0; nt < 4; nt++) {
            int col = n0 + warpN * 32 + nt * 8 + tig * 2;
            if (HOUT) {
                __half* Ch = (__half*)Cv;
                if (row0 < M) {
                    *(__half2*)(Ch + (size_t)row0 * N + col) =
                        __floats2half2_rn(acc[mt][nt][0] * s0, acc[mt][nt][1] * s0);
                }
                if (row1 < M) {
                    *(__half2*)(Ch + (size_t)row1 * N + col) =
                        __floats2half2_rn(acc[mt][nt][2] * s1, acc[mt][nt][3] * s1);
                }
            } else {
                float* C = (float*)Cv;
                if (row0 < M) {
                    float2 v = {acc[mt][nt][0] * s0, acc[mt][nt][1] * s0};
                    *(float2*)(C + (size_t)row0 * N + col) = v;
                }
                if (row1 < M) {
                    float2 v = {acc[mt][nt][2] * s1, acc[mt][nt][3] * s1};
                    *(float2*)(C + (size_t)row1 * N + col) = v;
                }
            }
        }
    }
}

// ----------------------------------------------------------------------------
// pull aggregation + bias + exact GELU, fp16 input (layer 1)
// Out[d,:] = gelu( dis[d] * (Hs[d,:] + sum_{s in N(d)} Hs[s,:]) + bias )
// TPG threads per node; each thread owns 4 columns = 1 uint2 of half2 pairs.
// ----------------------------------------------------------------------------
__device__ __forceinline__ void h4acc(float4& a, uint2 v) {
    float2 f0 = __half22float2(*(__half2*)&v.x);
    float2 f1 = __half22float2(*(__half2*)&v.y);
    a.x += f0.x; a.y += f0.y; a.z += f1.x; a.w += f1.y;
}

template <int TPG>
__global__ __launch_bounds__(256)
void agg_gelu_h_kernel(const __half* __restrict__ Hs, const float* __restrict__ bias,
                       float* __restrict__ Out, int n) {
    int gid = (int)(blockIdx.x * blockDim.x + threadIdx.x) / TPG;
    int t   = threadIdx.x & (TPG - 1);
    if (gid >= n) return;

    const uint2* H4 = (const uint2*)Hs;   // 4 halves per uint2; row stride = TPG
    int beg = g_rowptr[gid];
    int end = g_rowptr[gid + 1];

    float4 a0 = make_float4(0.f, 0.f, 0.f, 0.f);
    float4 a1 = a0, a2 = a0, a3 = a0;
    h4acc(a0, H4[(size_t)gid * TPG + t]);   // self-loop

    int p = beg;
    for (; p + 3 < end; p += 4) {
        int s0 = g_col[p];
        int s1 = g_col[p + 1];
        int s2 = g_col[p + 2];
        int s3 = g_col[p + 3];
        h4acc(a0, H4[(size_t)s0 * TPG + t]);
        h4acc(a1, H4[(size_t)s1 * TPG + t]);
        h4acc(a2, H4[(size_t)s2 * TPG + t]);
        h4acc(a3, H4[(size_t)s3 * TPG + t]);
    }
    for (; p < end; p++)
        h4acc(a0, H4[(size_t)g_col[p] * TPG + t]);

    float4 acc = make_float4(a0.x + a1.x + a2.x + a3.x,
                             a0.y + a1.y + a2.y + a3.y,
                             a0.z + a1.z + a2.z + a3.z,
                             a0.w + a1.w + a2.w + a3.w);
    float dd = g_dis[gid];
    float4 bb = ((const float4*)bias)[t];

    float x0 = acc.x * dd + bb.x;
    float x1 = acc.y * dd + bb.y;
    float x2 = acc.z * dd + bb.z;
    float x3 = acc.w * dd + bb.w;
    const float inv_sqrt2 = 0.70710678118654752f;
    float4 o;
    o.x = 0.5f * x0 * (1.0f + erff(x0 * inv_sqrt2));
    o.y = 0.5f * x1 * (1.0f + erff(x1 * inv_sqrt2));
    o.z = 0.5f * x2 * (1.0f + erff(x2 * inv_sqrt2));
    o.w = 0.5f * x3 * (1.0f + erff(x3 * inv_sqrt2));
    ((float4*)Out)[(size_t)gid * TPG + t] = o;
}

// ----------------------------------------------------------------------------
// pull aggregation + bias + exact GELU, fp32 input (layer 2, unchanged)
// ----------------------------------------------------------------------------
__device__ __forceinline__ float4 f4add(float4 a, float4 b) {
    return make_float4(a.x + b.x, a.y + b.y, a.z + b.z, a.w + b.w);
}

template <int TPG>
__global__ __launch_bounds__(256)
void agg_gelu_kernel(const float* __restrict__ Hs, const float* __restrict__ bias,
                     float* __restrict__ Out, int n) {
    int gid = (int)(blockIdx.x * blockDim.x + threadIdx.x) / TPG;
    int t   = threadIdx.x & (TPG - 1);
    if (gid >= n) return;

    const float4* H4 = (const float4*)Hs;
    int beg = g_rowptr[gid];
    int end = g_rowptr[gid + 1];

    float4 a0 = H4[(size_t)gid * TPG + t];
    float4 a1 = make_float4(0.f, 0.f, 0.f, 0.f);
    float4 a2 = a1, a3 = a1;

    int p = beg;
    for (; p + 3 < end; p += 4) {
        int s0 = g_col[p];
        int s1 = g_col[p + 1];
        int s2 = g_col[p + 2];
        int s3 = g_col[p + 3];
        a0 = f4add(a0, H4[(size_t)s0 * TPG + t]);
        a1 = f4add(a1, H4[(size_t)s1 * TPG + t]);
        a2 = f4add(a2, H4[(size_t)s2 * TPG + t]);
        a3 = f4add(a3, H4[(size_t)s3 * TPG + t]);
    }
    for (; p < end; p++)
        a0 = f4add(a0, H4[(size_t)g_col[p] * TPG + t]);

    float4 acc = f4add(f4add(a0, a1), f4add(a2, a3));
    float dd = g_dis[gid];
    float4 bb = ((const float4*)bias)[t];

    float x0 = acc.x * dd + bb.x;
    float x1 = acc.y * dd + bb.y;
    float x2 = acc.z * dd + bb.z;
    float x3 = acc.w * dd + bb.w;
    const float inv_sqrt2 = 0.70710678118654752f;
    float4 o;
    o.x = 0.5f * x0 * (1.0f + erff(x0 * inv_sqrt2));
    o.y = 0.5f * x1 * (1.0f + erff(x1 * inv_sqrt2));
    o.z = 0.5f * x2 * (1.0f + erff(x2 * inv_sqrt2));
    o.w = 0.5f * x3 * (1.0f + erff(x3 * inv_sqrt2));
    ((float4*)Out)[(size_t)gid * TPG + t] = o;
}

// ----------------------------------------------------------------------------
extern "C" void kernel_launch(void* const* d_in, const int* in_sizes, int n_in,
                              void* d_out, int out_size) {
    const float* node_emb = (const float*)d_in[0];   // [N, 256]
    const float* W1       = (const float*)d_in[1];   // [256, 256]
    const float* b1       = (const float*)d_in[2];   // [256]
    const float* W2       = (const float*)d_in[3];   // [256, 128]
    const float* b2       = (const float*)d_in[4];   // [128]
    const int*   eidx     = (const int*)d_in[5];     // [2, E]

    int N = in_sizes[0] / EMB;
    int E = in_sizes[5] / 2;
    const int* src = eidx;
    const int* dst = eidx + E;

    __half* H1h = nullptr; float* A1 = nullptr; float* H2 = nullptr;
    cudaGetSymbolAddress((void**)&H1h, g_H1h);
    cudaGetSymbolAddress((void**)&A1, g_A1);
    cudaGetSymbolAddress((void**)&H2, g_H2);
    float* outp = (float*)d_out;

    // one-time side stream + events (deterministic; no device memory)
    static cudaStream_t sB = nullptr;
    static cudaEvent_t evFork = nullptr, evCsr = nullptr;
    if (sB == nullptr) {
        cudaStreamCreateWithFlags(&sB, cudaStreamNonBlocking);
        cudaEventCreateWithFlags(&evFork, cudaEventDisableTiming);
        cudaEventCreateWithFlags(&evCsr, cudaEventDisableTiming);
    }

    int nblk_scan = (N + SCAN_B - 1) / SCAN_B;

    // ---- degrees + dis on MAIN stream (GEMM1 epilogue needs g_dis) ----
    zero_deg_kernel<<<(N + 255) / 256, 256>>>(N);
    count_deg_kernel<<<(E + 255) / 256, 256>>>(dst, E);
    compute_dis_kernel<<<(N + 255) / 256, 256>>>(N);

    // ---- fork: scan + CSR fill on side stream, hidden under GEMM1 ----
    cudaEventRecord(evFork, 0);
    cudaStreamWaitEvent(sB, evFork, 0);
    scan_phase1_kernel<<<nblk_scan, SCAN_B, 0, sB>>>(N);
    scan_phase2_kernel<<<1, 64, 0, sB>>>(nblk_scan);
    scan_phase3_kernel<<<nblk_scan, SCAN_B, 0, sB>>>(N, nblk_scan);
    fill_csr_kernel<<<(E + 255) / 256, 256, 0, sB>>>(src, dst, E);
    cudaEventRecord(evCsr, sB);

    // ---- layer 1 GEMM (concurrent with scan/fill), fp16 output ----
    {
        dim3 grid(MID / BN, (N + BM - 1) / BM);
        gemm_bf16_scale_kernel<true><<<grid, 256>>>(node_emb, W1, H1h, N, MID, EMB);
    }

    // join: aggregation needs rowptr/col
    cudaStreamWaitEvent(0, evCsr, 0);
    {
        const int TPG = MID / 4;   // 64
        int groups_per_blk = 256 / TPG;
        int nblk = (N + groups_per_blk - 1) / groups_per_blk;
        agg_gelu_h_kernel<TPG><<<nblk, 256>>>(H1h, b1, A1, N);
    }

    // ---- layer 2 (fp32 end-to-end) ----
    {
        dim3 grid(OUTD / BN, (N + BM - 1) / BM);
        gemm_bf16_scale_kernel<false><<<grid, 256>>>(A1, W2, H2, N, OUTD, MID);
    }
    {
        const int TPG = OUTD / 4;  // 32
        int groups_per_blk = 256 / TPG;
        int nblk = (N + groups_per_blk - 1) / groups_per_blk;
        agg_gelu_kernel<TPG><<<nblk, 256>>>(H2, b2, outp, N);
    }
}

// round 15
// speedup vs baseline: 1.1667x; 1.0026x over previous
#include <cuda_runtime.h>
#include <cuda_bf16.h>
#include <cuda_fp16.h>
#include <math.h>
#include <stdint.h>

#define NMAX   50000
#define EMAX   1048576
#define EMB    256
#define MID    256
#define OUTD   128
#define SCAN_B 1024
#define NBLK_SCAN ((NMAX + SCAN_B - 1) / SCAN_B)   // 49

// ---- scratch (static device globals; no runtime allocation) ----
__device__ __half g_H1h[NMAX * MID];   // dis .* (node_emb @ W1), fp16
__device__ float  g_A1[NMAX * MID];    // gelu(agg) -> layer-2 input
__device__ __half g_H2h[NMAX * OUTD];  // dis .* (X1 @ W2), fp16
__device__ float  g_dis[NMAX];         // D^-1/2 (in-degree + self loop)
__device__ int    g_deg[NMAX];
__device__ int    g_rowptr[NMAX + 1];
__device__ int    g_cur[NMAX];
__device__ int    g_col[EMAX];
__device__ int    g_blocksum[NBLK_SCAN + 1];

// ----------------------------------------------------------------------------
// degree / normalization
// ----------------------------------------------------------------------------
__global__ void zero_deg_kernel(int n) {
    int i = blockIdx.x * blockDim.x + threadIdx.x;
    if (i < n) g_deg[i] = 0;
}

__global__ void count_deg_kernel(const int* __restrict__ dst, int E) {
    int e = blockIdx.x * blockDim.x + threadIdx.x;
    if (e < E) atomicAdd(&g_deg[dst[e]], 1);
}

__global__ void compute_dis_kernel(int n) {
    int i = blockIdx.x * blockDim.x + threadIdx.x;
    if (i < n) g_dis[i] = rsqrtf((float)(g_deg[i] + 1));  // +1 = self loop
}

// ----------------------------------------------------------------------------
// multi-block exclusive scan of g_deg -> g_rowptr
// ----------------------------------------------------------------------------
__global__ __launch_bounds__(SCAN_B)
void scan_phase1_kernel(int n) {
    __shared__ int s[SCAN_B];
    int i = blockIdx.x * SCAN_B + threadIdx.x;
    int v = (i < n) ? g_deg[i] : 0;
    s[threadIdx.x] = v;
    __syncthreads();
#pragma unroll
    for (int off = 1; off < SCAN_B; off <<= 1) {
        int t = (threadIdx.x >= off) ? s[threadIdx.x - off] : 0;
        __syncthreads();
        s[threadIdx.x] += t;
        __syncthreads();
    }
    if (i < n) g_rowptr[i] = s[threadIdx.x] - v;
    if (threadIdx.x == SCAN_B - 1) g_blocksum[blockIdx.x] = s[SCAN_B - 1];
}

__global__ __launch_bounds__(64)
void scan_phase2_kernel(int nblk) {
    __shared__ int s[64];
    int v = (threadIdx.x < nblk) ? g_blocksum[threadIdx.x] : 0;
    s[threadIdx.x] = v;
    __syncthreads();
#pragma unroll
    for (int off = 1; off < 64; off <<= 1) {
        int t = (threadIdx.x >= off) ? s[threadIdx.x - off] : 0;
        __syncthreads();
        s[threadIdx.x] += t;
        __syncthreads();
    }
    if (threadIdx.x < nblk) g_blocksum[threadIdx.x] = s[threadIdx.x] - v;
    if (threadIdx.x == 63) g_blocksum[nblk] = s[63];
}

__global__ __launch_bounds__(SCAN_B)
void scan_phase3_kernel(int n, int nblk) {
    int i = blockIdx.x * SCAN_B + threadIdx.x;
    if (i < n) {
        int ex = g_rowptr[i] + g_blocksum[blockIdx.x];
        g_rowptr[i] = ex;
        g_cur[i] = ex;
    }
    if (i == 0) g_rowptr[n] = g_blocksum[nblk];
}

// ----------------------------------------------------------------------------
// CSR fill
// ----------------------------------------------------------------------------
__global__ void fill_csr_kernel(const int* __restrict__ src,
                                const int* __restrict__ dst, int E) {
    int e = blockIdx.x * blockDim.x + threadIdx.x;
    if (e < E) {
        int d = dst[e];
        int pos = atomicAdd(&g_cur[d], 1);
        g_col[pos] = src[e];
    }
}

// ----------------------------------------------------------------------------
// 3x-bf16 mma.sync GEMM (m16n8k16), hi/mid packed uint2 in smem:
//   C[m,:] = dis[m] * (A @ B)[m,:]   -> fp16 output
// BM=128, BN=64, BK=16; 256 threads (8 warps, 4x2 warp grid, 32x32 per warp).
// ----------------------------------------------------------------------------
#define BM 128
#define BN 64
#define BK 16
#define ASTR 12
#define BSTR 68

__device__ __forceinline__ void split2(float f0, float f1, uint32_t& hi, uint32_t& mid) {
    __nv_bfloat16 h0 = __float2bfloat16(f0);
    __nv_bfloat16 h1 = __float2bfloat16(f1);
    float r0 = f0 - __bfloat162float(h0);
    float r1 = f1 - __bfloat162float(h1);
    __nv_bfloat162 hp = __nv_bfloat162(h0, h1);
    __nv_bfloat162 mp = __nv_bfloat162(__float2bfloat16(r0), __float2bfloat16(r1));
    hi  = *(uint32_t*)&hp;
    mid = *(uint32_t*)&mp;
}

__device__ __forceinline__ void mma_bf16(float* d, const uint32_t* a, const uint32_t* b) {
    asm volatile(
        "mma.sync.aligned.m16n8k16.row.col.f32.bf16.bf16.f32 "
        "{%0,%1,%2,%3}, {%4,%5,%6,%7}, {%8,%9}, {%0,%1,%2,%3};\n"
        : "+f"(d[0]), "+f"(d[1]), "+f"(d[2]), "+f"(d[3])
        : "r"(a[0]), "r"(a[1]), "r"(a[2]), "r"(a[3]),
          "r"(b[0]), "r"(b[1]));
}

__global__ __launch_bounds__(256)
void gemm_bf16_scale_kernel(const float* __restrict__ A, const float* __restrict__ B,
                            __half* __restrict__ C, int M, int N, int K) {
    __shared__ uint2 Ahl[BM][ASTR];     // 12 KB
    __shared__ uint2 Bhl[BK / 2][BSTR]; // 4.25 KB

    int tid  = threadIdx.x;
    int lane = tid & 31;
    int wid  = tid >> 5;
    int gID  = lane >> 2;
    int tig  = lane & 3;
    int warpM = wid >> 1;
    int warpN = wid & 1;

    int m0 = blockIdx.y * BM;
    int n0 = blockIdx.x * BN;

    int aRow = tid >> 1;
    int akk  = (tid & 1) * 8;
    int akp  = (tid & 1) * 4;
    int bkp  = (tid & 127) >> 4;
    int bn   = (tid & 15) * 4;

    float acc[2][4][4];
#pragma unroll
    for (int mt = 0; mt < 2; mt++)
#pragma unroll
        for (int nt = 0; nt < 4; nt++)
#pragma unroll
            for (int r = 0; r < 4; r++) acc[mt][nt][r] = 0.0f;

    int nC = K / BK;

    float4 pa0, pa1, pb0, pb1;
    {
        int gm = m0 + aRow;
        if (gm < M) {
            const float* ap = A + (size_t)gm * K + akk;
            pa0 = *(const float4*)(ap);
            pa1 = *(const float4*)(ap + 4);
        } else {
            pa0 = pa1 = make_float4(0.f, 0.f, 0.f, 0.f);
        }
        if (tid < 128) {
            const float* bp = B + (size_t)(2 * bkp) * N + n0 + bn;
            pb0 = *(const float4*)(bp);
            pb1 = *(const float4*)(bp + N);
        }
    }

    for (int c = 0; c < nC; c++) {
        {
            float va[8] = {pa0.x, pa0.y, pa0.z, pa0.w, pa1.x, pa1.y, pa1.z, pa1.w};
#pragma unroll
            for (int j = 0; j < 4; j++) {
                uint32_t hi, mid;
                split2(va[2 * j], va[2 * j + 1], hi, mid);
                Ahl[aRow][akp + j] = make_uint2(hi, mid);
            }
            if (tid < 128) {
                float b0[4] = {pb0.x, pb0.y, pb0.z, pb0.w};
                float b1[4] = {pb1.x, pb1.y, pb1.z, pb1.w};
#pragma unroll
                for (int j = 0; j < 4; j++) {
                    uint32_t hi, mid;
                    split2(b0[j], b1[j], hi, mid);
                    Bhl[bkp][bn + j] = make_uint2(hi, mid);
                }
            }
        }
        __syncthreads();

        if (c + 1 < nC) {
            int k0 = (c + 1) * BK;
            int gm = m0 + aRow;
            if (gm < M) {
                const float* ap = A + (size_t)gm * K + k0 + akk;
                pa0 = *(const float4*)(ap);
                pa1 = *(const float4*)(ap + 4);
            } else {
                pa0 = pa1 = make_float4(0.f, 0.f, 0.f, 0.f);
            }
            if (tid < 128) {
                const float* bp = B + (size_t)(k0 + 2 * bkp) * N + n0 + bn;
                pb0 = *(const float4*)(bp);
                pb1 = *(const float4*)(bp + N);
            }
        }

        {
            uint32_t ah[2][4], am[2][4];
#pragma unroll
            for (int mt = 0; mt < 2; mt++) {
                int r = warpM * 32 + mt * 16 + gID;
                uint2 q0 = Ahl[r][tig];
                uint2 q1 = Ahl[r + 8][tig];
                uint2 q2 = Ahl[r][tig + 4];
                uint2 q3 = Ahl[r + 8][tig + 4];
                ah[mt][0] = q0.x; am[mt][0] = q0.y;
                ah[mt][1] = q1.x; am[mt][1] = q1.y;
                ah[mt][2] = q2.x; am[mt][2] = q2.y;
                ah[mt][3] = q3.x; am[mt][3] = q3.y;
            }
            uint32_t bh[4][2], bm[4][2];
#pragma unroll
            for (int nt = 0; nt < 4; nt++) {
                int n = warpN * 32 + nt * 8 + gID;
                uint2 p0 = Bhl[tig][n];
                uint2 p1 = Bhl[tig + 4][n];
                bh[nt][0] = p0.x; bm[nt][0] = p0.y;
                bh[nt][1] = p1.x; bm[nt][1] = p1.y;
            }
#pragma unroll
            for (int mt = 0; mt < 2; mt++)
#pragma unroll
                for (int nt = 0; nt < 4; nt++) {
                    mma_bf16(acc[mt][nt], ah[mt], bh[nt]);
                    mma_bf16(acc[mt][nt], ah[mt], bm[nt]);
                    mma_bf16(acc[mt][nt], am[mt], bh[nt]);
                }
        }
        __syncthreads();
    }

    // ---- epilogue: scale by dis[row], store fp16 ----
#pragma unroll
    for (int mt = 0; mt < 2; mt++) {
        int row0 = m0 + warpM * 32 + mt * 16 + gID;
        int row1 = row0 + 8;
        float s0 = (row0 < M) ? g_dis[row0] : 0.0f;
        float s1 = (row1 < M) ? g_dis[row1] : 0.0f;
#pragma unroll
        for (int nt = 0; nt < 4; nt++) {
            int col = n0 + warpN * 32 + nt * 8 + tig * 2;
            if (row0 < M) {
                *(__half2*)(C + (size_t)row0 * N + col) =
                    __floats2half2_rn(acc[mt][nt][0] * s0, acc[mt][nt][1] * s0);
            }
            if (row1 < M) {
                *(__half2*)(C + (size_t)row1 * N + col) =
                    __floats2half2_rn(acc[mt][nt][2] * s1, acc[mt][nt][3] * s1);
            }
        }
    }
}

// ----------------------------------------------------------------------------
// pull aggregation + bias + exact GELU, fp16 input, fp32 output
// Out[d,:] = gelu( dis[d] * (Hs[d,:] + sum_{s in N(d)} Hs[s,:]) + bias )
// TPG threads per node; each thread owns 4 columns = 1 uint2 of half2 pairs.
// ----------------------------------------------------------------------------
__device__ __forceinline__ void h4acc(float4& a, uint2 v) {
    float2 f0 = __half22float2(*(__half2*)&v.x);
    float2 f1 = __half22float2(*(__half2*)&v.y);
    a.x += f0.x; a.y += f0.y; a.z += f1.x; a.w += f1.y;
}

template <int TPG>
__global__ __launch_bounds__(256)
void agg_gelu_h_kernel(const __half* __restrict__ Hs, const float* __restrict__ bias,
                       float* __restrict__ Out, int n) {
    int gid = (int)(blockIdx.x * blockDim.x + threadIdx.x) / TPG;
    int t   = threadIdx.x & (TPG - 1);
    if (gid >= n) return;

    const uint2* H4 = (const uint2*)Hs;   // 4 halves per uint2; row stride = TPG
    int beg = g_rowptr[gid];
    int end = g_rowptr[gid + 1];

    float4 a0 = make_float4(0.f, 0.f, 0.f, 0.f);
    float4 a1 = a0, a2 = a0, a3 = a0;
    h4acc(a0, H4[(size_t)gid * TPG + t]);   // self-loop

    int p = beg;
    for (; p + 3 < end; p += 4) {
        int s0 = g_col[p];
        int s1 = g_col[p + 1];
        int s2 = g_col[p + 2];
        int s3 = g_col[p + 3];
        h4acc(a0, H4[(size_t)s0 * TPG + t]);
        h4acc(a1, H4[(size_t)s1 * TPG + t]);
        h4acc(a2, H4[(size_t)s2 * TPG + t]);
        h4acc(a3, H4[(size_t)s3 * TPG + t]);
    }
    for (; p < end; p++)
        h4acc(a0, H4[(size_t)g_col[p] * TPG + t]);

    float4 acc = make_float4(a0.x + a1.x + a2.x + a3.x,
                             a0.y + a1.y + a2.y + a3.y,
                             a0.z + a1.z + a2.z + a3.z,
                             a0.w + a1.w + a2.w + a3.w);
    float dd = g_dis[gid];
    float4 bb = ((const float4*)bias)[t];

    float x0 = acc.x * dd + bb.x;
    float x1 = acc.y * dd + bb.y;
    float x2 = acc.z * dd + bb.z;
    float x3 = acc.w * dd + bb.w;
    const float inv_sqrt2 = 0.70710678118654752f;
    float4 o;
    o.x = 0.5f * x0 * (1.0f + erff(x0 * inv_sqrt2));
    o.y = 0.5f * x1 * (1.0f + erff(x1 * inv_sqrt2));
    o.z = 0.5f * x2 * (1.0f + erff(x2 * inv_sqrt2));
    o.w = 0.5f * x3 * (1.0f + erff(x3 * inv_sqrt2));
    ((float4*)Out)[(size_t)gid * TPG + t] = o;
}

// ----------------------------------------------------------------------------
extern "C" void kernel_launch(void* const* d_in, const int* in_sizes, int n_in,
                              void* d_out, int out_size) {
    const float* node_emb = (const float*)d_in[0];   // [N, 256]
    const float* W1       = (const float*)d_in[1];   // [256, 256]
    const float* b1       = (const float*)d_in[2];   // [256]
    const float* W2       = (const float*)d_in[3];   // [256, 128]
    const float* b2       = (const float*)d_in[4];   // [128]
    const int*   eidx     = (const int*)d_in[5];     // [2, E]

    int N = in_sizes[0] / EMB;
    int E = in_sizes[5] / 2;
    const int* src = eidx;
    const int* dst = eidx + E;

    __half* H1h = nullptr; float* A1 = nullptr; __half* H2h = nullptr;
    cudaGetSymbolAddress((void**)&H1h, g_H1h);
    cudaGetSymbolAddress((void**)&A1, g_A1);
    cudaGetSymbolAddress((void**)&H2h, g_H2h);
    float* outp = (float*)d_out;

    // one-time side stream + events (deterministic; no device memory)
    static cudaStream_t sB = nullptr;
    static cudaEvent_t evFork = nullptr, evCsr = nullptr;
    if (sB == nullptr) {
        cudaStreamCreateWithFlags(&sB, cudaStreamNonBlocking);
        cudaEventCreateWithFlags(&evFork, cudaEventDisableTiming);
        cudaEventCreateWithFlags(&evCsr, cudaEventDisableTiming);
    }

    int nblk_scan = (N + SCAN_B - 1) / SCAN_B;

    // ---- degrees + dis on MAIN stream (GEMM1 epilogue needs g_dis) ----
    zero_deg_kernel<<<(N + 255) / 256, 256>>>(N);
    count_deg_kernel<<<(E + 255) / 256, 256>>>(dst, E);
    compute_dis_kernel<<<(N + 255) / 256, 256>>>(N);

    // ---- fork: scan + CSR fill on side stream, hidden under GEMM1 ----
    cudaEventRecord(evFork, 0);
    cudaStreamWaitEvent(sB, evFork, 0);
    scan_phase1_kernel<<<nblk_scan, SCAN_B, 0, sB>>>(N);
    scan_phase2_kernel<<<1, 64, 0, sB>>>(nblk_scan);
    scan_phase3_kernel<<<nblk_scan, SCAN_B, 0, sB>>>(N, nblk_scan);
    fill_csr_kernel<<<(E + 255) / 256, 256, 0, sB>>>(src, dst, E);
    cudaEventRecord(evCsr, sB);

    // ---- layer 1 GEMM (concurrent with scan/fill), fp16 output ----
    {
        dim3 grid(MID / BN, (N + BM - 1) / BM);
        gemm_bf16_scale_kernel<<<grid, 256>>>(node_emb, W1, H1h, N, MID, EMB);
    }

    // join: aggregation needs rowptr/col
    cudaStreamWaitEvent(0, evCsr, 0);
    {
        const int TPG = MID / 4;   // 64
        int groups_per_blk = 256 / TPG;
        int nblk = (N + groups_per_blk - 1) / groups_per_blk;
        agg_gelu_h_kernel<TPG><<<nblk, 256>>>(H1h, b1, A1, N);
    }

    // ---- layer 2, fp16 intermediate ----
    {
        dim3 grid(OUTD / BN, (N + BM - 1) / BM);
        gemm_bf16_scale_kernel<<<grid, 256>>>(A1, W2, H2h, N, OUTD, MID);
    }
    {
        const int TPG = OUTD / 4;  // 32
        int groups_per_blk = 256 / TPG;
        int nblk = (N + groups_per_blk - 1) / groups_per_blk;
        agg_gelu_h_kernel<TPG><<<nblk, 256>>>(H2h, b2, outp, N);
    }
}

// round 16
// speedup vs baseline: 1.6005x; 1.3718x over previous
#include <cuda_runtime.h>
#include <cuda_fp16.h>
#include <math.h>
#include <stdint.h>

#define NMAX   50000
#define EMAX   1048576
#define EMB    256
#define MID    256
#define OUTD   128
#define SCAN_B 1024
#define NBLK_SCAN ((NMAX + SCAN_B - 1) / SCAN_B)   // 49

// ---- scratch (static device globals; no runtime allocation) ----
__device__ __half g_H1h[NMAX * MID];   // dis .* (node_emb @ W1), fp16
__device__ __half g_A1h[NMAX * MID];   // gelu(agg), fp16 (layer-2 A operand)
__device__ __half g_H2h[NMAX * OUTD];  // dis .* (X1 @ W2), fp16
__device__ float  g_dis[NMAX];
__device__ int    g_deg[NMAX];
__device__ int    g_rowptr[NMAX + 1];
__device__ int    g_cur[NMAX];
__device__ int    g_col[EMAX];
__device__ int    g_blocksum[NBLK_SCAN + 1];

// ----------------------------------------------------------------------------
// degree / normalization
// ----------------------------------------------------------------------------
__global__ void zero_deg_kernel(int n) {
    int i = blockIdx.x * blockDim.x + threadIdx.x;
    if (i < n) g_deg[i] = 0;
}

__global__ void count_deg_kernel(const int* __restrict__ dst, int E) {
    int e = blockIdx.x * blockDim.x + threadIdx.x;
    if (e < E) atomicAdd(&g_deg[dst[e]], 1);
}

__global__ void compute_dis_kernel(int n) {
    int i = blockIdx.x * blockDim.x + threadIdx.x;
    if (i < n) g_dis[i] = rsqrtf((float)(g_deg[i] + 1));  // +1 = self loop
}

// ----------------------------------------------------------------------------
// multi-block exclusive scan of g_deg -> g_rowptr
// ----------------------------------------------------------------------------
__global__ __launch_bounds__(SCAN_B)
void scan_phase1_kernel(int n) {
    __shared__ int s[SCAN_B];
    int i = blockIdx.x * SCAN_B + threadIdx.x;
    int v = (i < n) ? g_deg[i] : 0;
    s[threadIdx.x] = v;
    __syncthreads();
#pragma unroll
    for (int off = 1; off < SCAN_B; off <<= 1) {
        int t = (threadIdx.x >= off) ? s[threadIdx.x - off] : 0;
        __syncthreads();
        s[threadIdx.x] += t;
        __syncthreads();
    }
    if (i < n) g_rowptr[i] = s[threadIdx.x] - v;
    if (threadIdx.x == SCAN_B - 1) g_blocksum[blockIdx.x] = s[SCAN_B - 1];
}

__global__ __launch_bounds__(64)
void scan_phase2_kernel(int nblk) {
    __shared__ int s[64];
    int v = (threadIdx.x < nblk) ? g_blocksum[threadIdx.x] : 0;
    s[threadIdx.x] = v;
    __syncthreads();
#pragma unroll
    for (int off = 1; off < 64; off <<= 1) {
        int t = (threadIdx.x >= off) ? s[threadIdx.x - off] : 0;
        __syncthreads();
        s[threadIdx.x] += t;
        __syncthreads();
    }
    if (threadIdx.x < nblk) g_blocksum[threadIdx.x] = s[threadIdx.x] - v;
    if (threadIdx.x == 63) g_blocksum[nblk] = s[63];
}

__global__ __launch_bounds__(SCAN_B)
void scan_phase3_kernel(int n, int nblk) {
    int i = blockIdx.x * SCAN_B + threadIdx.x;
    if (i < n) {
        int ex = g_rowptr[i] + g_blocksum[blockIdx.x];
        g_rowptr[i] = ex;
        g_cur[i] = ex;
    }
    if (i == 0) g_rowptr[n] = g_blocksum[nblk];
}

// ----------------------------------------------------------------------------
// CSR fill
// ----------------------------------------------------------------------------
__global__ void fill_csr_kernel(const int* __restrict__ src,
                                const int* __restrict__ dst, int E) {
    int e = blockIdx.x * blockDim.x + threadIdx.x;
    if (e < E) {
        int d = dst[e];
        int pos = atomicAdd(&g_cur[d], 1);
        g_col[pos] = src[e];
    }
}

// ----------------------------------------------------------------------------
// single-term fp16 mma.sync GEMM (m16n8k16, fp32 accum):
//   C[m,:] = dis[m] * (A @ B)[m,:]   -> fp16 output
// BM=128, BN=64, BK=16; 256 threads (8 warps, 4x2 warp grid, 32x32 per warp).
// AHALF: A operand already fp16 [M][K]; else fp32 (converted in loader).
// B always fp32 [K][N] (weights), converted in loader.
// ----------------------------------------------------------------------------
#define BM 128
#define BN 64
#define BK 16
#define ASTRH 12   // uint (half2) per A row: (12g+t) mod 32 all-distinct
#define BSTRH 72   // uint (half2) per B kpair row: 72 mod 32 = 8 -> (8t+g) distinct

__device__ __forceinline__ void mma_f16(float* d, const uint32_t* a, const uint32_t* b) {
    asm volatile(
        "mma.sync.aligned.m16n8k16.row.col.f32.f16.f16.f32 "
        "{%0,%1,%2,%3}, {%4,%5,%6,%7}, {%8,%9}, {%0,%1,%2,%3};\n"
        : "+f"(d[0]), "+f"(d[1]), "+f"(d[2]), "+f"(d[3])
        : "r"(a[0]), "r"(a[1]), "r"(a[2]), "r"(a[3]),
          "r"(b[0]), "r"(b[1]));
}

template <bool AHALF>
__global__ __launch_bounds__(256)
void gemm_f16_scale_kernel(const void* __restrict__ Av, const float* __restrict__ B,
                           __half* __restrict__ C, int M, int N, int K) {
    __shared__ uint32_t Ah[BM][ASTRH];     // 6 KB
    __shared__ uint32_t Bh[BK / 2][BSTRH]; // 2.25 KB

    int tid  = threadIdx.x;
    int lane = tid & 31;
    int wid  = tid >> 5;
    int gID  = lane >> 2;
    int tig  = lane & 3;
    int warpM = wid >> 1;
    int warpN = wid & 1;

    int m0 = blockIdx.y * BM;
    int n0 = blockIdx.x * BN;

    int aRow = tid >> 1;
    int akk  = (tid & 1) * 8;     // element offset within chunk (8 of 16)
    int akp  = (tid & 1) * 4;     // kpair offset (4 of 8)
    int bkp  = (tid & 127) >> 4;  // 0..7
    int bn   = (tid & 15) * 4;    // 0..60

    float acc[2][4][4];
#pragma unroll
    for (int mt = 0; mt < 2; mt++)
#pragma unroll
        for (int nt = 0; nt < 4; nt++)
#pragma unroll
            for (int r = 0; r < 4; r++) acc[mt][nt][r] = 0.0f;

    int nC = K / BK;

    // prefetch regs
    float4 pa0, pa1;        // fp32 A path
    uint4  pah;             // fp16 A path (8 halves)
    float4 pb0, pb1;

    {
        int gm = m0 + aRow;
        if (AHALF) {
            const __half* Ahp = (const __half*)Av;
            if (gm < M) pah = *(const uint4*)(Ahp + (size_t)gm * K + akk);
            else        pah = make_uint4(0, 0, 0, 0);
        } else {
            const float* A = (const float*)Av;
            if (gm < M) {
                const float* ap = A + (size_t)gm * K + akk;
                pa0 = *(const float4*)(ap);
                pa1 = *(const float4*)(ap + 4);
            } else {
                pa0 = pa1 = make_float4(0.f, 0.f, 0.f, 0.f);
            }
        }
        if (tid < 128) {
            const float* bp = B + (size_t)(2 * bkp) * N + n0 + bn;
            pb0 = *(const float4*)(bp);
            pb1 = *(const float4*)(bp + N);
        }
    }

    for (int c = 0; c < nC; c++) {
        // ---- store prefetched chunk to smem ----
        if (AHALF) {
            *(uint4*)&Ah[aRow][akp] = pah;
        } else {
            float va[8] = {pa0.x, pa0.y, pa0.z, pa0.w, pa1.x, pa1.y, pa1.z, pa1.w};
            uint32_t u[4];
#pragma unroll
            for (int j = 0; j < 4; j++) {
                __half2 h = __floats2half2_rn(va[2 * j], va[2 * j + 1]);
                u[j] = *(uint32_t*)&h;
            }
            *(uint4*)&Ah[aRow][akp] = make_uint4(u[0], u[1], u[2], u[3]);
        }
        if (tid < 128) {
            float b0[4] = {pb0.x, pb0.y, pb0.z, pb0.w};   // k = 2*bkp
            float b1[4] = {pb1.x, pb1.y, pb1.z, pb1.w};   // k = 2*bkp+1
            uint32_t u[4];
#pragma unroll
            for (int j = 0; j < 4; j++) {
                __half2 h = __floats2half2_rn(b0[j], b1[j]);
                u[j] = *(uint32_t*)&h;
            }
            *(uint4*)&Bh[bkp][bn] = make_uint4(u[0], u[1], u[2], u[3]);
        }
        __syncthreads();

        // ---- prefetch next chunk ----
        if (c + 1 < nC) {
            int k0 = (c + 1) * BK;
            int gm = m0 + aRow;
            if (AHALF) {
                const __half* Ahp = (const __half*)Av;
                if (gm < M) pah = *(const uint4*)(Ahp + (size_t)gm * K + k0 + akk);
                else        pah = make_uint4(0, 0, 0, 0);
            } else {
                const float* A = (const float*)Av;
                if (gm < M) {
                    const float* ap = A + (size_t)gm * K + k0 + akk;
                    pa0 = *(const float4*)(ap);
                    pa1 = *(const float4*)(ap + 4);
                } else {
                    pa0 = pa1 = make_float4(0.f, 0.f, 0.f, 0.f);
                }
            }
            if (tid < 128) {
                const float* bp = B + (size_t)(k0 + 2 * bkp) * N + n0 + bn;
                pb0 = *(const float4*)(bp);
                pb1 = *(const float4*)(bp + N);
            }
        }

        // ---- compute: one m16n8k16 step covers the chunk ----
        {
            uint32_t af[2][4];
#pragma unroll
            for (int mt = 0; mt < 2; mt++) {
                int r = warpM * 32 + mt * 16 + gID;
                af[mt][0] = Ah[r][tig];
                af[mt][1] = Ah[r + 8][tig];
                af[mt][2] = Ah[r][tig + 4];
                af[mt][3] = Ah[r + 8][tig + 4];
            }
            uint32_t bf[4][2];
#pragma unroll
            for (int nt = 0; nt < 4; nt++) {
                int n = warpN * 32 + nt * 8 + gID;
                bf[nt][0] = Bh[tig][n];
                bf[nt][1] = Bh[tig + 4][n];
            }
#pragma unroll
            for (int mt = 0; mt < 2; mt++)
#pragma unroll
                for (int nt = 0; nt < 4; nt++)
                    mma_f16(acc[mt][nt], af[mt], bf[nt]);
        }
        __syncthreads();
    }

    // ---- epilogue: scale by dis[row], store fp16 ----
#pragma unroll
    for (int mt = 0; mt < 2; mt++) {
        int row0 = m0 + warpM * 32 + mt * 16 + gID;
        int row1 = row0 + 8;
        float s0 = (row0 < M) ? g_dis[row0] : 0.0f;
        float s1 = (row1 < M) ? g_dis[row1] : 0.0f;
#pragma unroll
        for (int nt = 0; nt < 4; nt++) {
            int col = n0 + warpN * 32 + nt * 8 + tig * 2;
            if (row0 < M) {
                *(__half2*)(C + (size_t)row0 * N + col) =
                    __floats2half2_rn(acc[mt][nt][0] * s0, acc[mt][nt][1] * s0);
            }
            if (row1 < M) {
                *(__half2*)(C + (size_t)row1 * N + col) =
                    __floats2half2_rn(acc[mt][nt][2] * s1, acc[mt][nt][3] * s1);
            }
        }
    }
}

// ----------------------------------------------------------------------------
// pull aggregation + bias + exact GELU, fp16 input.
// HOUT=true: fp16 output (packed half2 x2); HOUT=false: fp32 output.
// Out[d,:] = gelu( dis[d] * (Hs[d,:] + sum_{s in N(d)} Hs[s,:]) + bias )
// ----------------------------------------------------------------------------
__device__ __forceinline__ void h4acc(float4& a, uint2 v) {
    float2 f0 = __half22float2(*(__half2*)&v.x);
    float2 f1 = __half22float2(*(__half2*)&v.y);
    a.x += f0.x; a.y += f0.y; a.z += f1.x; a.w += f1.y;
}

template <int TPG, bool HOUT>
__global__ __launch_bounds__(256)
void agg_gelu_h_kernel(const __half* __restrict__ Hs, const float* __restrict__ bias,
                       void* __restrict__ Out, int n) {
    int gid = (int)(blockIdx.x * blockDim.x + threadIdx.x) / TPG;
    int t   = threadIdx.x & (TPG - 1);
    if (gid >= n) return;

    const uint2* H4 = (const uint2*)Hs;   // 4 halves per uint2; row stride = TPG
    int beg = g_rowptr[gid];
    int end = g_rowptr[gid + 1];

    float4 a0 = make_float4(0.f, 0.f, 0.f, 0.f);
    float4 a1 = a0, a2 = a0, a3 = a0;
    h4acc(a0, H4[(size_t)gid * TPG + t]);   // self-loop

    int p = beg;
    for (; p + 3 < end; p += 4) {
        int s0 = g_col[p];
        int s1 = g_col[p + 1];
        int s2 = g_col[p + 2];
        int s3 = g_col[p + 3];
        h4acc(a0, H4[(size_t)s0 * TPG + t]);
        h4acc(a1, H4[(size_t)s1 * TPG + t]);
        h4acc(a2, H4[(size_t)s2 * TPG + t]);
        h4acc(a3, H4[(size_t)s3 * TPG + t]);
    }
    for (; p < end; p++)
        h4acc(a0, H4[(size_t)g_col[p] * TPG + t]);

    float4 acc = make_float4(a0.x + a1.x + a2.x + a3.x,
                             a0.y + a1.y + a2.y + a3.y,
                             a0.z + a1.z + a2.z + a3.z,
                             a0.w + a1.w + a2.w + a3.w);
    float dd = g_dis[gid];
    float4 bb = ((const float4*)bias)[t];

    float x0 = acc.x * dd + bb.x;
    float x1 = acc.y * dd + bb.y;
    float x2 = acc.z * dd + bb.z;
    float x3 = acc.w * dd + bb.w;
    const float inv_sqrt2 = 0.70710678118654752f;
    float o0 = 0.5f * x0 * (1.0f + erff(x0 * inv_sqrt2));
    float o1 = 0.5f * x1 * (1.0f + erff(x1 * inv_sqrt2));
    float o2 = 0.5f * x2 * (1.0f + erff(x2 * inv_sqrt2));
    float o3 = 0.5f * x3 * (1.0f + erff(x3 * inv_sqrt2));

    if (HOUT) {
        __half2 h01 = __floats2half2_rn(o0, o1);
        __half2 h23 = __floats2half2_rn(o2, o3);
        ((uint2*)Out)[(size_t)gid * TPG + t] =
            make_uint2(*(uint32_t*)&h01, *(uint32_t*)&h23);
    } else {
        ((float4*)Out)[(size_t)gid * TPG + t] = make_float4(o0, o1, o2, o3);
    }
}

// ----------------------------------------------------------------------------
extern "C" void kernel_launch(void* const* d_in, const int* in_sizes, int n_in,
                              void* d_out, int out_size) {
    const float* node_emb = (const float*)d_in[0];   // [N, 256]
    const float* W1       = (const float*)d_in[1];   // [256, 256]
    const float* b1       = (const float*)d_in[2];   // [256]
    const float* W2       = (const float*)d_in[3];   // [256, 128]
    const float* b2       = (const float*)d_in[4];   // [128]
    const int*   eidx     = (const int*)d_in[5];     // [2, E]

    int N = in_sizes[0] / EMB;
    int E = in_sizes[5] / 2;
    const int* src = eidx;
    const int* dst = eidx + E;

    __half *H1h = nullptr, *A1h = nullptr, *H2h = nullptr;
    cudaGetSymbolAddress((void**)&H1h, g_H1h);
    cudaGetSymbolAddress((void**)&A1h, g_A1h);
    cudaGetSymbolAddress((void**)&H2h, g_H2h);
    float* outp = (float*)d_out;

    // one-time side stream + events (deterministic; no device memory)
    static cudaStream_t sB = nullptr;
    static cudaEvent_t evFork = nullptr, evCsr = nullptr;
    if (sB == nullptr) {
        cudaStreamCreateWithFlags(&sB, cudaStreamNonBlocking);
        cudaEventCreateWithFlags(&evFork, cudaEventDisableTiming);
        cudaEventCreateWithFlags(&evCsr, cudaEventDisableTiming);
    }

    int nblk_scan = (N + SCAN_B - 1) / SCAN_B;

    // ---- degrees + dis on MAIN stream (GEMM1 epilogue needs g_dis) ----
    zero_deg_kernel<<<(N + 255) / 256, 256>>>(N);
    count_deg_kernel<<<(E + 255) / 256, 256>>>(dst, E);
    compute_dis_kernel<<<(N + 255) / 256, 256>>>(N);

    // ---- fork: scan + CSR fill on side stream, hidden under GEMM1 ----
    cudaEventRecord(evFork, 0);
    cudaStreamWaitEvent(sB, evFork, 0);
    scan_phase1_kernel<<<nblk_scan, SCAN_B, 0, sB>>>(N);
    scan_phase2_kernel<<<1, 64, 0, sB>>>(nblk_scan);
    scan_phase3_kernel<<<nblk_scan, SCAN_B, 0, sB>>>(N, nblk_scan);
    fill_csr_kernel<<<(E + 255) / 256, 256, 0, sB>>>(src, dst, E);
    cudaEventRecord(evCsr, sB);

    // ---- layer 1 GEMM (fp32 A), concurrent with scan/fill ----
    {
        dim3 grid(MID / BN, (N + BM - 1) / BM);
        gemm_f16_scale_kernel<false><<<grid, 256>>>(node_emb, W1, H1h, N, MID, EMB);
    }

    // join: aggregation needs rowptr/col
    cudaStreamWaitEvent(0, evCsr, 0);
    {
        const int TPG = MID / 4;   // 64
        int groups_per_blk = 256 / TPG;
        int nblk = (N + groups_per_blk - 1) / groups_per_blk;
        agg_gelu_h_kernel<TPG, true><<<nblk, 256>>>(H1h, b1, A1h, N);
    }

    // ---- layer 2 (fp16 A operand) ----
    {
        dim3 grid(OUTD / BN, (N + BM - 1) / BM);
        gemm_f16_scale_kernel<true><<<grid, 256>>>(A1h, W2, H2h, N, OUTD, MID);
    }
    {
        const int TPG = OUTD / 4;  // 32
        int groups_per_blk = 256 / TPG;
        int nblk = (N + groups_per_blk - 1) / groups_per_blk;
        agg_gelu_h_kernel<TPG, false><<<nblk, 256>>>(H2h, b2, outp, N);
    }
}

// round 17
// speedup vs baseline: 1.6885x; 1.0550x over previous
#include <cuda_runtime.h>
#include <cuda_fp16.h>
#include <math.h>
#include <stdint.h>

#define NMAX   50000
#define EMAX   1048576
#define EMB    256
#define MID    256
#define OUTD   128
#define SCAN_B 1024
#define NBLK_SCAN ((NMAX + SCAN_B - 1) / SCAN_B)   // 49

// ---- scratch (static device globals; no runtime allocation) ----
__device__ __half g_H1h[NMAX * MID];   // dis .* (node_emb @ W1), fp16
__device__ __half g_A1h[NMAX * MID];   // gelu(agg), fp16 (layer-2 A operand)
__device__ __half g_H2h[NMAX * OUTD];  // dis .* (X1 @ W2), fp16
__device__ float  g_dis[NMAX];
__device__ int    g_deg[NMAX];
__device__ int    g_rowptr[NMAX + 1];
__device__ int    g_cur[NMAX];
__device__ int    g_col[EMAX];
__device__ int    g_blocksum[NBLK_SCAN + 1];

// ----------------------------------------------------------------------------
// degree / normalization
// ----------------------------------------------------------------------------
__global__ void zero_deg_kernel(int n) {
    int i = blockIdx.x * blockDim.x + threadIdx.x;
    if (i < n) g_deg[i] = 0;
}

__global__ void count_deg_kernel(const int* __restrict__ dst, int E) {
    int e = blockIdx.x * blockDim.x + threadIdx.x;
    if (e < E) atomicAdd(&g_deg[dst[e]], 1);
}

__global__ void compute_dis_kernel(int n) {
    int i = blockIdx.x * blockDim.x + threadIdx.x;
    if (i < n) g_dis[i] = rsqrtf((float)(g_deg[i] + 1));  // +1 = self loop
}

// ----------------------------------------------------------------------------
// multi-block exclusive scan of g_deg -> g_rowptr
// ----------------------------------------------------------------------------
__global__ __launch_bounds__(SCAN_B)
void scan_phase1_kernel(int n) {
    __shared__ int s[SCAN_B];
    int i = blockIdx.x * SCAN_B + threadIdx.x;
    int v = (i < n) ? g_deg[i] : 0;
    s[threadIdx.x] = v;
    __syncthreads();
#pragma unroll
    for (int off = 1; off < SCAN_B; off <<= 1) {
        int t = (threadIdx.x >= off) ? s[threadIdx.x - off] : 0;
        __syncthreads();
        s[threadIdx.x] += t;
        __syncthreads();
    }
    if (i < n) g_rowptr[i] = s[threadIdx.x] - v;
    if (threadIdx.x == SCAN_B - 1) g_blocksum[blockIdx.x] = s[SCAN_B - 1];
}

__global__ __launch_bounds__(64)
void scan_phase2_kernel(int nblk) {
    __shared__ int s[64];
    int v = (threadIdx.x < nblk) ? g_blocksum[threadIdx.x] : 0;
    s[threadIdx.x] = v;
    __syncthreads();
#pragma unroll
    for (int off = 1; off < 64; off <<= 1) {
        int t = (threadIdx.x >= off) ? s[threadIdx.x - off] : 0;
        __syncthreads();
        s[threadIdx.x] += t;
        __syncthreads();
    }
    if (threadIdx.x < nblk) g_blocksum[threadIdx.x] = s[threadIdx.x] - v;
    if (threadIdx.x == 63) g_blocksum[nblk] = s[63];
}

__global__ __launch_bounds__(SCAN_B)
void scan_phase3_kernel(int n, int nblk) {
    int i = blockIdx.x * SCAN_B + threadIdx.x;
    if (i < n) {
        int ex = g_rowptr[i] + g_blocksum[blockIdx.x];
        g_rowptr[i] = ex;
        g_cur[i] = ex;
    }
    if (i == 0) g_rowptr[n] = g_blocksum[nblk];
}

// ----------------------------------------------------------------------------
// CSR fill
// ----------------------------------------------------------------------------
__global__ void fill_csr_kernel(const int* __restrict__ src,
                                const int* __restrict__ dst, int E) {
    int e = blockIdx.x * blockDim.x + threadIdx.x;
    if (e < E) {
        int d = dst[e];
        int pos = atomicAdd(&g_cur[d], 1);
        g_col[pos] = src[e];
    }
}

// ----------------------------------------------------------------------------
// single-term fp16 mma.sync GEMM (m16n8k16, fp32 accum):
//   C[m,:] = dis[m] * (A @ B)[m,:]   -> fp16 output
// BM=128, BN=128, BK=16; 256 threads, 8 warps (4x2 grid), warp tile 32x64.
// Register-prefetched global loads; AHALF selects fp16/fp32 A operand.
// ----------------------------------------------------------------------------
#define BM 128
#define BN 128
#define BK 16
#define ASTRH 12    // uint (half2) per A row: (12g+t) mod 32 all-distinct
#define BSTRH 136   // uint (half2) per B kpair row: 136 mod 32 = 8 -> conflict-free

__device__ __forceinline__ void mma_f16(float* d, const uint32_t* a, const uint32_t* b) {
    asm volatile(
        "mma.sync.aligned.m16n8k16.row.col.f32.f16.f16.f32 "
        "{%0,%1,%2,%3}, {%4,%5,%6,%7}, {%8,%9}, {%0,%1,%2,%3};\n"
        : "+f"(d[0]), "+f"(d[1]), "+f"(d[2]), "+f"(d[3])
        : "r"(a[0]), "r"(a[1]), "r"(a[2]), "r"(a[3]),
          "r"(b[0]), "r"(b[1]));
}

template <bool AHALF>
__global__ __launch_bounds__(256)
void gemm_f16_scale_kernel(const void* __restrict__ Av, const float* __restrict__ B,
                           __half* __restrict__ C, int M, int N, int K) {
    __shared__ uint32_t Ah[BM][ASTRH];     // 6 KB
    __shared__ uint32_t Bh[BK / 2][BSTRH]; // 4.25 KB

    int tid  = threadIdx.x;
    int lane = tid & 31;
    int wid  = tid >> 5;
    int gID  = lane >> 2;         // 0..7
    int tig  = lane & 3;          // 0..3
    int warpM = wid >> 1;         // 0..3 -> 32-row slab
    int warpN = wid & 1;          // 0..1 -> 64-col slab

    int m0 = blockIdx.y * BM;
    int n0 = blockIdx.x * BN;

    int aRow = tid >> 1;
    int akk  = (tid & 1) * 8;     // element offset within chunk
    int akp  = (tid & 1) * 4;     // kpair offset
    int bkp  = tid >> 5;          // 0..7 (all 256 threads)
    int bn   = (tid & 31) * 4;    // 0..124

    float acc[2][8][4];
#pragma unroll
    for (int mt = 0; mt < 2; mt++)
#pragma unroll
        for (int nt = 0; nt < 8; nt++)
#pragma unroll
            for (int r = 0; r < 4; r++) acc[mt][nt][r] = 0.0f;

    int nC = K / BK;

    // prefetch regs
    float4 pa0, pa1;        // fp32 A path
    uint4  pah;             // fp16 A path
    float4 pb0, pb1;

    {
        int gm = m0 + aRow;
        if (AHALF) {
            const __half* Ahp = (const __half*)Av;
            if (gm < M) pah = *(const uint4*)(Ahp + (size_t)gm * K + akk);
            else        pah = make_uint4(0, 0, 0, 0);
        } else {
            const float* A = (const float*)Av;
            if (gm < M) {
                const float* ap = A + (size_t)gm * K + akk;
                pa0 = *(const float4*)(ap);
                pa1 = *(const float4*)(ap + 4);
            } else {
                pa0 = pa1 = make_float4(0.f, 0.f, 0.f, 0.f);
            }
        }
        const float* bp = B + (size_t)(2 * bkp) * N + n0 + bn;
        pb0 = *(const float4*)(bp);
        pb1 = *(const float4*)(bp + N);
    }

    for (int c = 0; c < nC; c++) {
        // ---- store prefetched chunk to smem ----
        if (AHALF) {
            *(uint4*)&Ah[aRow][akp] = pah;
        } else {
            float va[8] = {pa0.x, pa0.y, pa0.z, pa0.w, pa1.x, pa1.y, pa1.z, pa1.w};
            uint32_t u[4];
#pragma unroll
            for (int j = 0; j < 4; j++) {
                __half2 h = __floats2half2_rn(va[2 * j], va[2 * j + 1]);
                u[j] = *(uint32_t*)&h;
            }
            *(uint4*)&Ah[aRow][akp] = make_uint4(u[0], u[1], u[2], u[3]);
        }
        {
            float b0[4] = {pb0.x, pb0.y, pb0.z, pb0.w};   // k = 2*bkp
            float b1[4] = {pb1.x, pb1.y, pb1.z, pb1.w};   // k = 2*bkp+1
            uint32_t u[4];
#pragma unroll
            for (int j = 0; j < 4; j++) {
                __half2 h = __floats2half2_rn(b0[j], b1[j]);
                u[j] = *(uint32_t*)&h;
            }
            *(uint4*)&Bh[bkp][bn] = make_uint4(u[0], u[1], u[2], u[3]);
        }
        __syncthreads();

        // ---- prefetch next chunk ----
        if (c + 1 < nC) {
            int k0 = (c + 1) * BK;
            int gm = m0 + aRow;
            if (AHALF) {
                const __half* Ahp = (const __half*)Av;
                if (gm < M) pah = *(const uint4*)(Ahp + (size_t)gm * K + k0 + akk);
                else        pah = make_uint4(0, 0, 0, 0);
            } else {
                const float* A = (const float*)Av;
                if (gm < M) {
                    const float* ap = A + (size_t)gm * K + k0 + akk;
                    pa0 = *(const float4*)(ap);
                    pa1 = *(const float4*)(ap + 4);
                } else {
                    pa0 = pa1 = make_float4(0.f, 0.f, 0.f, 0.f);
                }
            }
            const float* bp = B + (size_t)(k0 + 2 * bkp) * N + n0 + bn;
            pb0 = *(const float4*)(bp);
            pb1 = *(const float4*)(bp + N);
        }

        // ---- compute: one m16n8k16 step covers the chunk ----
        {
            uint32_t af[2][4];
#pragma unroll
            for (int mt = 0; mt < 2; mt++) {
                int r = warpM * 32 + mt * 16 + gID;
                af[mt][0] = Ah[r][tig];
                af[mt][1] = Ah[r + 8][tig];
                af[mt][2] = Ah[r][tig + 4];
                af[mt][3] = Ah[r + 8][tig + 4];
            }
#pragma unroll
            for (int nt = 0; nt < 8; nt++) {
                int n = warpN * 64 + nt * 8 + gID;
                uint32_t bf[2];
                bf[0] = Bh[tig][n];
                bf[1] = Bh[tig + 4][n];
#pragma unroll
                for (int mt = 0; mt < 2; mt++)
                    mma_f16(acc[mt][nt], af[mt], bf);
            }
        }
        __syncthreads();
    }

    // ---- epilogue: scale by dis[row], store fp16 ----
#pragma unroll
    for (int mt = 0; mt < 2; mt++) {
        int row0 = m0 + warpM * 32 + mt * 16 + gID;
        int row1 = row0 + 8;
        float s0 = (row0 < M) ? g_dis[row0] : 0.0f;
        float s1 = (row1 < M) ? g_dis[row1] : 0.0f;
#pragma unroll
        for (int nt = 0; nt < 8; nt++) {
            int col = n0 + warpN * 64 + nt * 8 + tig * 2;
            if (row0 < M) {
                *(__half2*)(C + (size_t)row0 * N + col) =
                    __floats2half2_rn(acc[mt][nt][0] * s0, acc[mt][nt][1] * s0);
            }
            if (row1 < M) {
                *(__half2*)(C + (size_t)row1 * N + col) =
                    __floats2half2_rn(acc[mt][nt][2] * s1, acc[mt][nt][3] * s1);
            }
        }
    }
}

// ----------------------------------------------------------------------------
// pull aggregation + bias + exact GELU, fp16 input.
// HOUT=true: fp16 output (packed half2 x2); HOUT=false: fp32 output.
// Out[d,:] = gelu( dis[d] * (Hs[d,:] + sum_{s in N(d)} Hs[s,:]) + bias )
// ----------------------------------------------------------------------------
__device__ __forceinline__ void h4acc(float4& a, uint2 v) {
    float2 f0 = __half22float2(*(__half2*)&v.x);
    float2 f1 = __half22float2(*(__half2*)&v.y);
    a.x += f0.x; a.y += f0.y; a.z += f1.x; a.w += f1.y;
}

template <int TPG, bool HOUT>
__global__ __launch_bounds__(256)
void agg_gelu_h_kernel(const __half* __restrict__ Hs, const float* __restrict__ bias,
                       void* __restrict__ Out, int n) {
    int gid = (int)(blockIdx.x * blockDim.x + threadIdx.x) / TPG;
    int t   = threadIdx.x & (TPG - 1);
    if (gid >= n) return;

    const uint2* H4 = (const uint2*)Hs;   // 4 halves per uint2; row stride = TPG
    int beg = g_rowptr[gid];
    int end = g_rowptr[gid + 1];

    float4 a0 = make_float4(0.f, 0.f, 0.f, 0.f);
    float4 a1 = a0, a2 = a0, a3 = a0;
    h4acc(a0, H4[(size_t)gid * TPG + t]);   // self-loop

    int p = beg;
    for (; p + 3 < end; p += 4) {
        int s0 = g_col[p];
        int s1 = g_col[p + 1];
        int s2 = g_col[p + 2];
        int s3 = g_col[p + 3];
        h4acc(a0, H4[(size_t)s0 * TPG + t]);
        h4acc(a1, H4[(size_t)s1 * TPG + t]);
        h4acc(a2, H4[(size_t)s2 * TPG + t]);
        h4acc(a3, H4[(size_t)s3 * TPG + t]);
    }
    for (; p < end; p++)
        h4acc(a0, H4[(size_t)g_col[p] * TPG + t]);

    float4 acc = make_float4(a0.x + a1.x + a2.x + a3.x,
                             a0.y + a1.y + a2.y + a3.y,
                             a0.z + a1.z + a2.z + a3.z,
                             a0.w + a1.w + a2.w + a3.w);
    float dd = g_dis[gid];
    float4 bb = ((const float4*)bias)[t];

    float x0 = acc.x * dd + bb.x;
    float x1 = acc.y * dd + bb.y;
    float x2 = acc.z * dd + bb.z;
    float x3 = acc.w * dd + bb.w;
    const float inv_sqrt2 = 0.70710678118654752f;
    float o0 = 0.5f * x0 * (1.0f + erff(x0 * inv_sqrt2));
    float o1 = 0.5f * x1 * (1.0f + erff(x1 * inv_sqrt2));
    float o2 = 0.5f * x2 * (1.0f + erff(x2 * inv_sqrt2));
    float o3 = 0.5f * x3 * (1.0f + erff(x3 * inv_sqrt2));

    if (HOUT) {
        __half2 h01 = __floats2half2_rn(o0, o1);
        __half2 h23 = __floats2half2_rn(o2, o3);
        ((uint2*)Out)[(size_t)gid * TPG + t] =
            make_uint2(*(uint32_t*)&h01, *(uint32_t*)&h23);
    } else {
        ((float4*)Out)[(size_t)gid * TPG + t] = make_float4(o0, o1, o2, o3);
    }
}

// ----------------------------------------------------------------------------
extern "C" void kernel_launch(void* const* d_in, const int* in_sizes, int n_in,
                              void* d_out, int out_size) {
    const float* node_emb = (const float*)d_in[0];   // [N, 256]
    const float* W1       = (const float*)d_in[1];   // [256, 256]
    const float* b1       = (const float*)d_in[2];   // [256]
    const float* W2       = (const float*)d_in[3];   // [256, 128]
    const float* b2       = (const float*)d_in[4];   // [128]
    const int*   eidx     = (const int*)d_in[5];     // [2, E]

    int N = in_sizes[0] / EMB;
    int E = in_sizes[5] / 2;
    const int* src = eidx;
    const int* dst = eidx + E;

    __half *H1h = nullptr, *A1h = nullptr, *H2h = nullptr;
    cudaGetSymbolAddress((void**)&H1h, g_H1h);
    cudaGetSymbolAddress((void**)&A1h, g_A1h);
    cudaGetSymbolAddress((void**)&H2h, g_H2h);
    float* outp = (float*)d_out;

    // one-time side stream + events (deterministic; no device memory)
    static cudaStream_t sB = nullptr;
    static cudaEvent_t evFork = nullptr, evCsr = nullptr;
    if (sB == nullptr) {
        cudaStreamCreateWithFlags(&sB, cudaStreamNonBlocking);
        cudaEventCreateWithFlags(&evFork, cudaEventDisableTiming);
        cudaEventCreateWithFlags(&evCsr, cudaEventDisableTiming);
    }

    int nblk_scan = (N + SCAN_B - 1) / SCAN_B;

    // ---- degrees + dis on MAIN stream (GEMM1 epilogue needs g_dis) ----
    zero_deg_kernel<<<(N + 255) / 256, 256>>>(N);
    count_deg_kernel<<<(E + 255) / 256, 256>>>(dst, E);
    compute_dis_kernel<<<(N + 255) / 256, 256>>>(N);

    // ---- fork: scan + CSR fill on side stream, hidden under GEMM1 ----
    cudaEventRecord(evFork, 0);
    cudaStreamWaitEvent(sB, evFork, 0);
    scan_phase1_kernel<<<nblk_scan, SCAN_B, 0, sB>>>(N);
    scan_phase2_kernel<<<1, 64, 0, sB>>>(nblk_scan);
    scan_phase3_kernel<<<nblk_scan, SCAN_B, 0, sB>>>(N, nblk_scan);
    fill_csr_kernel<<<(E + 255) / 256, 256, 0, sB>>>(src, dst, E);
    cudaEventRecord(evCsr, sB);

    // ---- layer 1 GEMM (fp32 A), concurrent with scan/fill ----
    {
        dim3 grid(MID / BN, (N + BM - 1) / BM);
        gemm_f16_scale_kernel<false><<<grid, 256>>>(node_emb, W1, H1h, N, MID, EMB);
    }

    // join: aggregation needs rowptr/col
    cudaStreamWaitEvent(0, evCsr, 0);
    {
        const int TPG = MID / 4;   // 64
        int groups_per_blk = 256 / TPG;
        int nblk = (N + groups_per_blk - 1) / groups_per_blk;
        agg_gelu_h_kernel<TPG, true><<<nblk, 256>>>(H1h, b1, A1h, N);
    }

    // ---- layer 2 (fp16 A operand) ----
    {
        dim3 grid(OUTD / BN, (N + BM - 1) / BM);
        gemm_f16_scale_kernel<true><<<grid, 256>>>(A1h, W2, H2h, N, OUTD, MID);
    }
    {
        const int TPG = OUTD / 4;  // 32
        int groups_per_blk = 256 / TPG;
        int nblk = (N + groups_per_blk - 1) / groups_per_blk;
        agg_gelu_h_kernel<TPG, false><<<nblk, 256>>>(H2h, b2, outp, N);
    }
}